// round 8
// baseline (speedup 1.0000x reference)
#include <cuda_runtime.h>
#include <cuda_bf16.h>
#include <cuda_fp16.h>
#include <math.h>
#include <stdint.h>

#define SDIM 768
#define CCH  128
#define NTOK (SDIM*SDIM)        // 589824 tokens
#define SELEM 75497472          // 128 * 589824
#define NSM   148

// Scratch: a as fp16 hi/lo (exact split), b as fp16 hi only
__device__ __half g_ahi[SELEM];
__device__ __half g_alo[SELEM];
__device__ __half g_bhi[SELEM];
__device__ float g_tri[SELEM];
__device__ float g_gate[SELEM];

// Prepped fp16 weights:
// g_wcI: 4 groups x 128 rows x 128 k; group g row 2r = wgi col(64g+r), row 2r+1 = wpi col(64g+r)
__device__ __half g_wcI[4*128*128];
__device__ __half g_wgo16[128*128];   // wgo^T [n][k]
__device__ __half g_wpo16[128*128];   // wpo^T [co][h]

__device__ __forceinline__ float sigmoidf_(float v) {
    return 1.f / (1.f + __expf(-v));
}
__device__ __forceinline__ uint32_t smem_u32(const void* p) {
    uint32_t a;
    asm("{ .reg .u64 t; cvta.to.shared.u64 t, %1; cvt.u32.u64 %0, t; }"
        : "=r"(a) : "l"(p));
    return a;
}
#define CP_ASYNC16(d, s)  asm volatile("cp.async.cg.shared.global [%0], [%1], 16;" :: "r"(d), "l"(s))
#define CP_COMMIT()       asm volatile("cp.async.commit_group;" ::: "memory")
#define CP_WAIT0()        asm volatile("cp.async.wait_group 0;" ::: "memory")
#define CP_WAIT1()        asm volatile("cp.async.wait_group 1;" ::: "memory")
#define CP_WAIT2()        asm volatile("cp.async.wait_group 2;" ::: "memory")

__device__ __forceinline__ void ldsm4(uint32_t* r, uint32_t addr) {
    asm volatile("ldmatrix.sync.aligned.m8n8.x4.shared.b16 {%0,%1,%2,%3}, [%4];"
        : "=r"(r[0]), "=r"(r[1]), "=r"(r[2]), "=r"(r[3]) : "r"(addr));
}
__device__ __forceinline__ void mma16816h(float* d, const uint32_t* a, const uint32_t* b) {
    asm volatile("mma.sync.aligned.m16n8k16.row.col.f32.f16.f16.f32 "
        "{%0,%1,%2,%3}, {%4,%5,%6,%7}, {%8,%9}, {%0,%1,%2,%3};"
        : "+f"(d[0]), "+f"(d[1]), "+f"(d[2]), "+f"(d[3])
        : "r"(a[0]), "r"(a[1]), "r"(a[2]), "r"(a[3]), "r"(b[0]), "r"(b[1]));
}
__device__ __forceinline__ uint32_t pack_split16(float v) {
    __half h = __float2half_rn(v);
    __half l = __float2half_rn(v - __half2float(h));
    return (uint32_t)__half_as_ushort(h) | ((uint32_t)__half_as_ushort(l) << 16);
}

// ---------------------------------------------------------------------------
// Kernel 0: weight prep.
// ---------------------------------------------------------------------------
__global__ void __launch_bounds__(256) prep_w_kernel(
    const float* __restrict__ wgi, const float* __restrict__ wpi,
    const float* __restrict__ wgo, const float* __restrict__ wpo)
{
    int idx = blockIdx.x*256 + threadIdx.x;   // 0..65535
    {
        int g = idx >> 14, rem = idx & 16383;
        int row = rem >> 7, k = rem & 127;
        int col = g*64 + (row >> 1);
        float v = (row & 1) ? wpi[k*256 + col] : wgi[k*256 + col];
        g_wcI[idx] = __float2half_rn(v);
    }
    if (idx < 16384) {
        int n = idx >> 7, k = idx & 127;
        g_wgo16[idx] = __float2half_rn(wgo[k*128 + n]);
        g_wpo16[idx] = __float2half_rn(wpo[k*128 + n]);
    }
}

// ---------------------------------------------------------------------------
// Kernel 1: proj3 — persistent; 128-token tiles; LN(x) + all projections.
// Per tile: 5 B-chunks streamed (double buffer), 2-pass fp16, two-phase
// transpose epilogue.
// ---------------------------------------------------------------------------
#define PROW   272
#define PTILE  (128*PROW)         // 34816
#define ATILE  (64*PROW)          // 17408
#define XROW   528
#define P3_AHI  0
#define P3_ALO  PTILE                      // 34816
#define P3_B    (2*PTILE)                  // 69632
#define P3_STG  (P3_B + 2*PTILE)           // 139264
#define P3_TP   (P3_STG + 128*XROW)        // 206848
#define P3_SMEM (P3_TP + 64*68*4)          // 224256
#define NP3     (NTOK/128)                 // 4608

__global__ void __launch_bounds__(256) proj3_kernel(
    const float* __restrict__ x, const float* __restrict__ mask,
    const float* __restrict__ nw, const float* __restrict__ nb)
{
    extern __shared__ char sm[];
    const uint32_t base = smem_u32(sm);
    const int tid = threadIdx.x;
    const int bid = blockIdx.x;

    const int wid  = tid >> 5;
    const int lane = tid & 31;
    const int wm     = wid >> 2;          // 0..1
    const int m_base = wm * 64;
    const int n_base = (wid & 3) * 32;
    const int a_row  = lane & 15;
    const int a_half = lane >> 4;
    const int b_quad = lane >> 3;
    const int b_row  = (b_quad >> 1)*8 + (lane & 7);
    const int b_half = b_quad & 1;

    const __half* csrc[5] = { g_wcI, g_wcI + 16384, g_wcI + 32768,
                              g_wcI + 49152, g_wgo16 };

    const float* xstg = (const float*)(sm + P3_STG);
    const int tl = tid >> 1, half = tid & 1;   // LN: 2 threads per token

    // first x tile (128 tokens)
    {
        int t0 = bid * 128;
        #pragma unroll
        for (int rep = 0; rep < 16; rep++) {
            int it = tid + rep*256;
            int row = it >> 5, q = it & 31;
            CP_ASYNC16(base + P3_STG + row*XROW + q*16,
                       x + (size_t)(t0 + row)*CCH + q*4);
        }
        CP_COMMIT();
        CP_WAIT0();
        __syncthreads();
    }

    for (int tile = bid; tile < NP3; tile += NSM) {
        const int t0 = tile * 128;

        // issue B0, B1
        #pragma unroll
        for (int cc = 0; cc < 2; cc++) {
            const __half* s = csrc[cc];
            uint32_t dst = base + P3_B + cc*PTILE;
            #pragma unroll
            for (int rep = 0; rep < 8; rep++) {
                int it = tid + rep*256;
                int row = it >> 4, q = it & 15;
                CP_ASYNC16(dst + row*PROW + q*16, (const char*)(s + row*128) + q*16);
            }
            CP_COMMIT();
        }

        // LN(x) -> split fp16 A (2 threads per token, 64 values each)
        {
            const float* xrow = xstg + tl*132 + half*64;
            float v[64];
            float s = 0.f;
            #pragma unroll
            for (int i = 0; i < 16; i++) {
                float4 f = *(const float4*)(xrow + i*4);
                v[i*4]=f.x; v[i*4+1]=f.y; v[i*4+2]=f.z; v[i*4+3]=f.w;
                s += f.x + f.y + f.z + f.w;
            }
            s += __shfl_xor_sync(0xFFFFFFFFu, s, 1);
            float m = s * (1.f/128.f);
            float q2 = 0.f;
            #pragma unroll
            for (int i = 0; i < 64; i++) { float d = v[i]-m; q2 += d*d; }
            q2 += __shfl_xor_sync(0xFFFFFFFFu, q2, 1);
            float rs = rsqrtf(q2 * (1.f/128.f) + 1e-5f);

            #pragma unroll
            for (int i = 0; i < 32; i++) {
                int k = half*64 + i*2;
                float v0 = (v[i*2]   - m)*rs*__ldg(&nw[k])   + __ldg(&nb[k]);
                float v1 = (v[i*2+1] - m)*rs*__ldg(&nw[k+1]) + __ldg(&nb[k+1]);
                __half h0 = __float2half_rn(v0);
                __half h1 = __float2half_rn(v1);
                __half2 hh; hh.x = h0; hh.y = h1;
                __half2 ll;
                ll.x = __float2half_rn(v0 - __half2float(h0));
                ll.y = __float2half_rn(v1 - __half2float(h1));
                *(__half2*)(sm + P3_AHI + tl*PROW + k*2) = hh;
                *(__half2*)(sm + P3_ALO + tl*PROW + k*2) = ll;
            }
        }
        __syncthreads();   // A visible; xstg reads done

        // issue next-tile x prefetch (group X)
        if (tile + NSM < NP3) {
            int nt0 = (tile + NSM) * 128;
            #pragma unroll
            for (int rep = 0; rep < 16; rep++) {
                int it = tid + rep*256;
                int row = it >> 5, q = it & 31;
                CP_ASYNC16(base + P3_STG + row*XROW + q*16,
                           x + (size_t)(nt0 + row)*CCH + q*4);
            }
        }
        CP_COMMIT();

        // chunk loop: ledger commits B0,B1,X,B2,B3,B4 -> waits 2,2,1,1,0
        #pragma unroll
        for (int c = 0; c < 5; c++) {
            if (c <= 1) CP_WAIT2();
            else if (c <= 3) CP_WAIT1();
            else CP_WAIT0();
            __syncthreads();

            const uint32_t sb = base + P3_B + (c&1)*PTILE;
            float acc[4][4][4];
            #pragma unroll
            for (int mt = 0; mt < 4; mt++)
                #pragma unroll
                for (int nt = 0; nt < 4; nt++)
                    #pragma unroll
                    for (int r = 0; r < 4; r++) acc[mt][nt][r] = 0.f;

            #pragma unroll
            for (int ks = 0; ks < 8; ks++) {
                const uint32_t koff = ks*32;
                uint32_t Ah[4][4], Al[4][4];
                #pragma unroll
                for (int mt = 0; mt < 4; mt++) {
                    uint32_t r = (m_base + mt*16 + a_row)*PROW + koff + a_half*16;
                    ldsm4(Ah[mt], base + P3_AHI + r);
                    ldsm4(Al[mt], base + P3_ALO + r);
                }
                uint32_t Bf[4][2];
                #pragma unroll
                for (int p = 0; p < 2; p++) {
                    uint32_t r = (n_base + p*16 + b_row)*PROW + koff + b_half*16;
                    uint32_t th[4];
                    ldsm4(th, sb + r);
                    Bf[2*p][0]   = th[0]; Bf[2*p][1]   = th[1];
                    Bf[2*p+1][0] = th[2]; Bf[2*p+1][1] = th[3];
                }
                #pragma unroll
                for (int mt = 0; mt < 4; mt++)
                    #pragma unroll
                    for (int nt = 0; nt < 4; nt++) mma16816h(acc[mt][nt], Ah[mt], Bf[nt]);
                #pragma unroll
                for (int mt = 0; mt < 4; mt++)
                    #pragma unroll
                    for (int nt = 0; nt < 4; nt++) mma16816h(acc[mt][nt], Al[mt], Bf[nt]);
            }
            __syncthreads();   // all warps done with buf (c&1)

            // issue B chunk c+2 into buf (c&1)
            if (c <= 2) {
                const __half* s = csrc[c+2];
                uint32_t dst = base + P3_B + (c&1)*PTILE;
                #pragma unroll
                for (int rep = 0; rep < 8; rep++) {
                    int it = tid + rep*256;
                    int row = it >> 4, q = it & 15;
                    CP_ASYNC16(dst + row*PROW + q*16, (const char*)(s + row*128) + q*16);
                }
                CP_COMMIT();
            }

            if (c < 4) {
                // a/b epilogue: two-phase transpose (64 tokens per phase)
                uint32_t* tp = (uint32_t*)(sm + P3_TP);
                const bool isA = (c < 2);
                const int cgl = (c & 1) * 64;
                #pragma unroll
                for (int ph = 0; ph < 2; ph++) {
                    if (wm == ph) {
                        #pragma unroll
                        for (int mt = 0; mt < 4; mt++) {
                            #pragma unroll
                            for (int rp = 0; rp < 2; rp++) {
                                int t_rel = mt*16 + rp*8 + (lane >> 2);     // 0..63
                                int t_loc = m_base + t_rel;                 // == ph*64 + t_rel
                                float mk = isA ? __ldg(&mask[t0 + t_loc]) : 1.f;
                                #pragma unroll
                                for (int nt = 0; nt < 4; nt++) {
                                    int c_loc = (n_base >> 1) + nt*4 + (lane & 3);
                                    float val = sigmoidf_(acc[mt][nt][rp*2]) * acc[mt][nt][rp*2+1] * mk;
                                    tp[c_loc*68 + t_rel] = pack_split16(val);
                                }
                            }
                        }
                    }
                    __syncthreads();

                    #pragma unroll
                    for (int rep = 0; rep < 8; rep++) {
                        int idx = tid + rep*256;        // 0..2047
                        int cl = idx >> 5, t2 = idx & 31;
                        uint32_t u0 = tp[cl*68 + t2*2];
                        uint32_t u1 = tp[cl*68 + t2*2 + 1];
                        uint32_t hi2 = (u0 & 0xFFFFu) | (u1 << 16);
                        size_t o = ((size_t)(cgl + cl)*NTOK + t0 + ph*64) >> 1;
                        if (isA) {
                            uint32_t lo2 = (u0 >> 16) | (u1 & 0xFFFF0000u);
                            ((uint32_t*)g_ahi)[o + t2] = hi2;
                            ((uint32_t*)g_alo)[o + t2] = lo2;
                        } else {
                            ((uint32_t*)g_bhi)[o + t2] = hi2;
                        }
                    }
                    __syncthreads();
                }
            } else {
                // out-gate epilogue: token-major sigmoid, direct stores
                #pragma unroll
                for (int mt = 0; mt < 4; mt++) {
                    #pragma unroll
                    for (int rp = 0; rp < 2; rp++) {
                        int t = t0 + m_base + mt*16 + rp*8 + (lane >> 2);
                        #pragma unroll
                        for (int nt = 0; nt < 4; nt++) {
                            int ch = n_base + nt*8 + (lane & 3)*2;
                            float2 f = make_float2(sigmoidf_(acc[mt][nt][rp*2]),
                                                   sigmoidf_(acc[mt][nt][rp*2+1]));
                            *(float2*)&g_gate[(size_t)t*CCH + ch] = f;
                        }
                    }
                }
            }
        }
    }
}

// ---------------------------------------------------------------------------
// Kernel 2: tri einsum, 2-pass split-fp16, triple-buffered. (unchanged)
// ---------------------------------------------------------------------------
#define ROWB    144
#define TILEB   (128*ROWB)          // 18432
#define CHUNK3  (3*TILEB)           // 55296

__device__ __forceinline__ void tri_load_chunk(
    uint32_t sbuf, const __half* s0, const __half* s1, const __half* s2,
    int kk, int tid)
{
    const __half* srcs[3] = {s0, s1, s2};
    #pragma unroll
    for (int rep = 0; rep < 12; rep++) {
        int it   = tid + rep*256;
        int tile = it >> 10;
        int row  = (it >> 3) & 127;
        int q8   = it & 7;
        const __half* gp = srcs[tile] + (size_t)row*SDIM + kk + q8*8;
        CP_ASYNC16(sbuf + tile*TILEB + row*ROWB + q8*16, gp);
    }
}

__global__ void __launch_bounds__(256) tri_mma_kernel()
{
    extern __shared__ char dynsm[];
    const uint32_t base = smem_u32(dynsm);

    const int tid  = threadIdx.x;
    const int wid  = tid >> 5;
    const int lane = tid & 31;
    const int m_base = (wid >> 2) * 64;
    const int n_base = (wid & 3) * 32;

    const int c  = blockIdx.y;
    const int i0 = (blockIdx.x / 6) * 128;
    const int j0 = (blockIdx.x % 6) * 128;

    const __half* sAh = g_ahi + (size_t)c*NTOK + (size_t)i0*SDIM;
    const __half* sAl = g_alo + (size_t)c*NTOK + (size_t)i0*SDIM;
    const __half* sBh = g_bhi + (size_t)c*NTOK + (size_t)j0*SDIM;

    float acc[4][4][4];
    #pragma unroll
    for (int mt = 0; mt < 4; mt++)
        #pragma unroll
        for (int nt = 0; nt < 4; nt++)
            #pragma unroll
            for (int r = 0; r < 4; r++) acc[mt][nt][r] = 0.f;

    const int a_row  = lane & 15;
    const int a_half = lane >> 4;
    const int b_quad = lane >> 3;
    const int b_row  = (b_quad >> 1) * 8 + (lane & 7);
    const int b_half = b_quad & 1;

    tri_load_chunk(base + 0*CHUNK3, sAh, sAl, sBh, 0,  tid); CP_COMMIT();
    tri_load_chunk(base + 1*CHUNK3, sAh, sAl, sBh, 64, tid); CP_COMMIT();

    for (int n = 0; n < 12; n++) {
        if (n + 2 < 12)
            tri_load_chunk(base + ((n+2)%3)*CHUNK3, sAh, sAl, sBh, (n+2)*64, tid);
        CP_COMMIT();
        CP_WAIT2();
        __syncthreads();

        const uint32_t sb = base + (n%3)*CHUNK3;
        #pragma unroll
        for (int ks = 0; ks < 4; ks++) {
            uint32_t Ah[4][4], Al[4][4], Bh[4][2];
            const uint32_t koff = ks*32;
            #pragma unroll
            for (int mt = 0; mt < 4; mt++) {
                uint32_t r = (m_base + mt*16 + a_row)*ROWB + koff + a_half*16;
                ldsm4(Ah[mt], sb + 0*TILEB + r);
                ldsm4(Al[mt], sb + 1*TILEB + r);
            }
            #pragma unroll
            for (int p = 0; p < 2; p++) {
                uint32_t r = (n_base + p*16 + b_row)*ROWB + koff + b_half*16;
                uint32_t th[4];
                ldsm4(th, sb + 2*TILEB + r);
                Bh[2*p][0]   = th[0]; Bh[2*p][1]   = th[1];
                Bh[2*p+1][0] = th[2]; Bh[2*p+1][1] = th[3];
            }
            #pragma unroll
            for (int mt = 0; mt < 4; mt++)
                #pragma unroll
                for (int nt = 0; nt < 4; nt++)
                    mma16816h(acc[mt][nt], Ah[mt], Bh[nt]);
            #pragma unroll
            for (int mt = 0; mt < 4; mt++)
                #pragma unroll
                for (int nt = 0; nt < 4; nt++)
                    mma16816h(acc[mt][nt], Al[mt], Bh[nt]);
        }
        __syncthreads();
    }

    float* T = g_tri + (size_t)c*NTOK;
    const int er = i0 + m_base + (lane >> 2);
    const int ec2 = j0 + n_base + (lane & 3)*2;
    #pragma unroll
    for (int mt = 0; mt < 4; mt++) {
        #pragma unroll
        for (int nt = 0; nt < 4; nt++) {
            int rr = er + mt*16;
            int cc = ec2 + nt*8;
            *(float2*)&T[(size_t)rr*SDIM + cc]     = make_float2(acc[mt][nt][0], acc[mt][nt][1]);
            *(float2*)&T[(size_t)(rr+8)*SDIM + cc] = make_float2(acc[mt][nt][2], acc[mt][nt][3]);
        }
    }
}

// ---------------------------------------------------------------------------
// Kernel 3: out_persist — 2-pass fp16, 64-token tiles, staged tri+gate.
// ---------------------------------------------------------------------------
#define OV_TRI   0                      // 128 x 272B  (tri [ch][t] f32)
#define OV_G0    34816                  // 64 x 528B   (gate [t][c] f32)
#define OV_G1    (OV_G0 + 33792)
#define OV_AHI   (OV_G1 + 33792)        // 64 x 272B
#define OV_ALO   (OV_AHI + ATILE)
#define OV_B     (OV_ALO + ATILE)       // 1 x PTILE (fp16 hi)
#define OV_SMEM  (OV_B + PTILE)         // 172032
#define NOTILE64 (NTOK/64)              // 9216

__global__ void __launch_bounds__(256) out_persist_kernel(
    const float* __restrict__ now, const float* __restrict__ nob,
    float* __restrict__ out)
{
    extern __shared__ char sm[];
    const uint32_t base = smem_u32(sm);
    const int tid = threadIdx.x;
    const int bid = blockIdx.x;

    // one-time B (wpo^T fp16 hi)
    #pragma unroll
    for (int rep = 0; rep < 8; rep++) {
        int it = tid + rep*256;
        int row = it >> 4, q = it & 15;
        CP_ASYNC16(base + OV_B + row*PROW + q*16,
                   (const char*)(g_wpo16 + row*128) + q*16);
    }
    // first tile: tri + gate
    {
        int t0 = bid * 64;
        #pragma unroll
        for (int rep = 0; rep < 8; rep++) {
            int it = tid + rep*256;
            int ch = it >> 4, q = it & 15;
            CP_ASYNC16(base + OV_TRI + ch*272 + q*16,
                       g_tri + (size_t)ch*NTOK + t0 + q*4);
        }
        #pragma unroll
        for (int rep = 0; rep < 8; rep++) {
            int it = tid + rep*256;
            int row = it >> 5, q = it & 31;
            CP_ASYNC16(base + OV_G0 + row*528 + q*16,
                       g_gate + (size_t)(t0 + row)*CCH + q*4);
        }
    }
    CP_COMMIT();

    const int wid  = tid >> 5;
    const int lane = tid & 31;
    const int m_base = (wid >> 2) * 32;
    const int n_base = (wid & 3) * 32;
    const int a_row  = lane & 15;
    const int a_half = lane >> 4;
    const int b_quad = lane >> 3;
    const int b_row  = (b_quad >> 1)*8 + (lane & 7);
    const int b_half = b_quad & 1;
    const int er = m_base + (lane >> 2);
    const int ec = n_base + (lane & 3)*2;

    const float* trs = (const float*)(sm + OV_TRI);
    const int tl = tid >> 2, qq = tid & 3;

    int ii = 0;
    for (int tile = bid; tile < NOTILE64; tile += NSM, ii++) {
        const int t0 = tile * 64;
        const int gbuf = ii & 1;
        CP_WAIT0();
        __syncthreads();

        // LN over channels -> split fp16 A [t][ch]
        {
            float s = 0.f;
            #pragma unroll 8
            for (int j = 0; j < 32; j++) s += trs[(qq*32 + j)*68 + tl];
            s += __shfl_xor_sync(0xFFFFFFFFu, s, 1);
            s += __shfl_xor_sync(0xFFFFFFFFu, s, 2);
            float m = s * (1.f/128.f);
            float q2 = 0.f;
            #pragma unroll 8
            for (int j = 0; j < 32; j++) {
                float d = trs[(qq*32 + j)*68 + tl] - m;
                q2 += d*d;
            }
            q2 += __shfl_xor_sync(0xFFFFFFFFu, q2, 1);
            q2 += __shfl_xor_sync(0xFFFFFFFFu, q2, 2);
            float rs = rsqrtf(q2 * (1.f/128.f) + 1e-5f);

            #pragma unroll
            for (int j = 0; j < 16; j++) {
                int ch = qq*32 + j*2;
                float v0 = (trs[ch*68 + tl]     - m)*rs*__ldg(&now[ch])   + __ldg(&nob[ch]);
                float v1 = (trs[(ch+1)*68 + tl] - m)*rs*__ldg(&now[ch+1]) + __ldg(&nob[ch+1]);
                __half h0 = __float2half_rn(v0);
                __half h1 = __float2half_rn(v1);
                __half2 hh; hh.x = h0; hh.y = h1;
                __half2 ll;
                ll.x = __float2half_rn(v0 - __half2float(h0));
                ll.y = __float2half_rn(v1 - __half2float(h1));
                *(__half2*)(sm + OV_AHI + tl*PROW + ch*2) = hh;
                *(__half2*)(sm + OV_ALO + tl*PROW + ch*2) = ll;
            }
        }
        __syncthreads();

        // prefetch next tri + gate (other gate buffer)
        if (tile + NSM < NOTILE64) {
            int nt0 = (tile + NSM) * 64;
            #pragma unroll
            for (int rep = 0; rep < 8; rep++) {
                int it = tid + rep*256;
                int ch = it >> 4, q = it & 15;
                CP_ASYNC16(base + OV_TRI + ch*272 + q*16,
                           g_tri + (size_t)ch*NTOK + nt0 + q*4);
            }
            uint32_t gdst = base + (gbuf ? OV_G0 : OV_G1);
            #pragma unroll
            for (int rep = 0; rep < 8; rep++) {
                int it = tid + rep*256;
                int row = it >> 5, q = it & 31;
                CP_ASYNC16(gdst + row*528 + q*16,
                           g_gate + (size_t)(nt0 + row)*CCH + q*4);
            }
        }
        CP_COMMIT();

        float acc[2][4][4];
        #pragma unroll
        for (int mt = 0; mt < 2; mt++)
            #pragma unroll
            for (int nt = 0; nt < 4; nt++)
                #pragma unroll
                for (int r = 0; r < 4; r++) acc[mt][nt][r] = 0.f;

        #pragma unroll
        for (int ks = 0; ks < 8; ks++) {
            const uint32_t koff = ks*32;
            uint32_t Ah[2][4], Al[2][4];
            #pragma unroll
            for (int mt = 0; mt < 2; mt++) {
                uint32_t r = (m_base + mt*16 + a_row)*PROW + koff + a_half*16;
                ldsm4(Ah[mt], base + OV_AHI + r);
                ldsm4(Al[mt], base + OV_ALO + r);
            }
            uint32_t Bf[4][2];
            #pragma unroll
            for (int p = 0; p < 2; p++) {
                uint32_t r = (n_base + p*16 + b_row)*PROW + koff + b_half*16;
                uint32_t th[4];
                ldsm4(th, base + OV_B + r);
                Bf[2*p][0]   = th[0]; Bf[2*p][1]   = th[1];
                Bf[2*p+1][0] = th[2]; Bf[2*p+1][1] = th[3];
            }
            #pragma unroll
            for (int mt = 0; mt < 2; mt++)
                #pragma unroll
                for (int nt = 0; nt < 4; nt++) mma16816h(acc[mt][nt], Ah[mt], Bf[nt]);
            #pragma unroll
            for (int mt = 0; mt < 2; mt++)
                #pragma unroll
                for (int nt = 0; nt < 4; nt++) mma16816h(acc[mt][nt], Al[mt], Bf[nt]);
        }

        const float* gst = (const float*)(sm + (gbuf ? OV_G1 : OV_G0));
        #pragma unroll
        for (int mt = 0; mt < 2; mt++) {
            #pragma unroll
            for (int rp = 0; rp < 2; rp++) {
                int t_loc = er + mt*16 + rp*8;
                #pragma unroll
                for (int nt = 0; nt < 4; nt++) {
                    int cc = ec + nt*8;
                    float2 gg = *(const float2*)&gst[t_loc*132 + cc];
                    float2 o = make_float2(acc[mt][nt][rp*2]   * gg.x,
                                           acc[mt][nt][rp*2+1] * gg.y);
                    *(float2*)&out[(size_t)(t0 + t_loc)*CCH + cc] = o;
                }
            }
        }
        __syncthreads();
    }
}

// ---------------------------------------------------------------------------
extern "C" void kernel_launch(void* const* d_in, const int* in_sizes, int n_in,
                              void* d_out, int out_size)
{
    const float* x    = (const float*)d_in[0];
    const float* mask = (const float*)d_in[1];
    const float* niw  = (const float*)d_in[2];
    const float* nib  = (const float*)d_in[3];
    const float* wgi  = (const float*)d_in[4];
    const float* wpi  = (const float*)d_in[5];
    const float* now  = (const float*)d_in[6];
    const float* nob  = (const float*)d_in[7];
    const float* wgo  = (const float*)d_in[8];
    const float* wpo  = (const float*)d_in[9];
    float* out = (float*)d_out;

    cudaFuncSetAttribute(proj3_kernel,
        cudaFuncAttributeMaxDynamicSharedMemorySize, P3_SMEM);
    cudaFuncSetAttribute(tri_mma_kernel,
        cudaFuncAttributeMaxDynamicSharedMemorySize, 3*CHUNK3);
    cudaFuncSetAttribute(out_persist_kernel,
        cudaFuncAttributeMaxDynamicSharedMemorySize, OV_SMEM);

    prep_w_kernel<<<256, 256>>>(wgi, wpi, wgo, wpo);
    proj3_kernel<<<NSM, 256, P3_SMEM>>>(x, mask, niw, nib);
    tri_mma_kernel<<<dim3(36, 128), 256, 3*CHUNK3>>>();
    out_persist_kernel<<<NSM, 256, OV_SMEM>>>(now, nob, out);
}

// round 9
// speedup vs baseline: 1.1569x; 1.1569x over previous
#include <cuda_runtime.h>
#include <cuda_bf16.h>
#include <cuda_fp16.h>
#include <math.h>
#include <stdint.h>

#define SDIM 768
#define CCH  128
#define NTOK (SDIM*SDIM)        // 589824 tokens
#define SELEM 75497472          // 128 * 589824
#define NSM   148

// Scratch: a as fp16 hi/lo (exact split), b as fp16 hi only
__device__ __half g_ahi[SELEM];
__device__ __half g_alo[SELEM];
__device__ __half g_bhi[SELEM];
__device__ float g_tri[SELEM];
__device__ float g_gate[SELEM];

// Prepped fp16 weights:
// g_wcI: 4 groups x 128 rows x 128 k; group g row 2r = wgi col(64g+r), row 2r+1 = wpi col(64g+r)
__device__ __half g_wcI[4*128*128];
__device__ __half g_wgo16[128*128];   // wgo^T [n][k]
__device__ __half g_wpo16[128*128];   // wpo^T [co][h]

__device__ __forceinline__ float sigmoidf_(float v) {
    return 1.f / (1.f + __expf(-v));
}
__device__ __forceinline__ uint32_t smem_u32(const void* p) {
    uint32_t a;
    asm("{ .reg .u64 t; cvta.to.shared.u64 t, %1; cvt.u32.u64 %0, t; }"
        : "=r"(a) : "l"(p));
    return a;
}
#define CP_ASYNC16(d, s)  asm volatile("cp.async.cg.shared.global [%0], [%1], 16;" :: "r"(d), "l"(s))
#define CP_COMMIT()       asm volatile("cp.async.commit_group;" ::: "memory")
#define CP_WAIT0()        asm volatile("cp.async.wait_group 0;" ::: "memory")
#define CP_WAIT2()        asm volatile("cp.async.wait_group 2;" ::: "memory")

__device__ __forceinline__ void ldsm4(uint32_t* r, uint32_t addr) {
    asm volatile("ldmatrix.sync.aligned.m8n8.x4.shared.b16 {%0,%1,%2,%3}, [%4];"
        : "=r"(r[0]), "=r"(r[1]), "=r"(r[2]), "=r"(r[3]) : "r"(addr));
}
__device__ __forceinline__ void mma16816h(float* d, const uint32_t* a, const uint32_t* b) {
    asm volatile("mma.sync.aligned.m16n8k16.row.col.f32.f16.f16.f32 "
        "{%0,%1,%2,%3}, {%4,%5,%6,%7}, {%8,%9}, {%0,%1,%2,%3};"
        : "+f"(d[0]), "+f"(d[1]), "+f"(d[2]), "+f"(d[3])
        : "r"(a[0]), "r"(a[1]), "r"(a[2]), "r"(a[3]), "r"(b[0]), "r"(b[1]));
}
__device__ __forceinline__ uint32_t pack_split16(float v) {
    __half h = __float2half_rn(v);
    __half l = __float2half_rn(v - __half2float(h));
    return (uint32_t)__half_as_ushort(h) | ((uint32_t)__half_as_ushort(l) << 16);
}

// ---------------------------------------------------------------------------
// Kernel 0: weight prep.
// ---------------------------------------------------------------------------
__global__ void __launch_bounds__(256) prep_w_kernel(
    const float* __restrict__ wgi, const float* __restrict__ wpi,
    const float* __restrict__ wgo, const float* __restrict__ wpo)
{
    int idx = blockIdx.x*256 + threadIdx.x;   // 0..65535
    {
        int g = idx >> 14, rem = idx & 16383;
        int row = rem >> 7, k = rem & 127;
        int col = g*64 + (row >> 1);
        float v = (row & 1) ? wpi[k*256 + col] : wgi[k*256 + col];
        g_wcI[idx] = __float2half_rn(v);
    }
    if (idx < 16384) {
        int n = idx >> 7, k = idx & 127;
        g_wgo16[idx] = __float2half_rn(wgo[k*128 + n]);
        g_wpo16[idx] = __float2half_rn(wpo[k*128 + n]);
    }
}

// ---------------------------------------------------------------------------
// Kernel 1: proj4 — persistent; 64-token tiles; ALL 5 weight chunks resident
// in smem. LN reads x directly via __ldg. 2-pass split-fp16 HMMA.
// ---------------------------------------------------------------------------
#define PROW   272
#define PTILE  (128*PROW)         // 34816
#define ATILE  (64*PROW)          // 17408
#define P4_AHI  0
#define P4_ALO  ATILE                      // 17408
#define P4_B    (2*ATILE)                  // 34816
#define P4_TP   (P4_B + 5*PTILE)           // 208896
#define P4_SMEM (P4_TP + 64*68*4)          // 226304
#define NP4     (NTOK/64)                  // 9216

__global__ void __launch_bounds__(256) proj4_kernel(
    const float* __restrict__ x, const float* __restrict__ mask,
    const float* __restrict__ nw, const float* __restrict__ nb)
{
    extern __shared__ char sm[];
    const uint32_t base = smem_u32(sm);
    const int tid = threadIdx.x;
    const int bid = blockIdx.x;

    const int wid  = tid >> 5;
    const int lane = tid & 31;
    const int m_base = (wid >> 2) * 32;   // 2 m-warps
    const int n_base = (wid & 3) * 32;    // 4 n-warps
    const int a_row  = lane & 15;
    const int a_half = lane >> 4;
    const int b_quad = lane >> 3;
    const int b_row  = (b_quad >> 1)*8 + (lane & 7);
    const int b_half = b_quad & 1;
    const int ec = n_base + (lane & 3)*2;

    // --- load ALL 5 B chunks once ---
    const __half* csrc[5] = { g_wcI, g_wcI + 16384, g_wcI + 32768,
                              g_wcI + 49152, g_wgo16 };
    for (int cc = 0; cc < 5; cc++) {
        const __half* s = csrc[cc];
        uint32_t dst = base + P4_B + cc*PTILE;
        #pragma unroll
        for (int rep = 0; rep < 8; rep++) {
            int it = tid + rep*256;
            int row = it >> 4, q = it & 15;
            CP_ASYNC16(dst + row*PROW + q*16, (const char*)(s + row*128) + q*16);
        }
    }
    CP_COMMIT();
    CP_WAIT0();
    __syncthreads();

    const int tl = tid >> 2, qq = tid & 3;    // LN: 4 threads per token

    for (int tile = bid; tile < NP4; tile += NSM) {
        const int t0 = tile * 64;

        // --- LN(x) direct from gmem -> split fp16 A ---
        {
            const float* xrow = x + (size_t)(t0 + tl)*CCH + qq*32;
            float v[32];
            float s = 0.f;
            #pragma unroll
            for (int i = 0; i < 8; i++) {
                float4 f = __ldg((const float4*)(xrow + i*4));
                v[i*4]=f.x; v[i*4+1]=f.y; v[i*4+2]=f.z; v[i*4+3]=f.w;
                s += f.x + f.y + f.z + f.w;
            }
            s += __shfl_xor_sync(0xFFFFFFFFu, s, 1);
            s += __shfl_xor_sync(0xFFFFFFFFu, s, 2);
            float m = s * (1.f/128.f);
            float q2 = 0.f;
            #pragma unroll
            for (int i = 0; i < 32; i++) { float d = v[i]-m; q2 += d*d; }
            q2 += __shfl_xor_sync(0xFFFFFFFFu, q2, 1);
            q2 += __shfl_xor_sync(0xFFFFFFFFu, q2, 2);
            float rs = rsqrtf(q2 * (1.f/128.f) + 1e-5f);

            #pragma unroll
            for (int i = 0; i < 16; i++) {
                int k = qq*32 + i*2;
                float v0 = (v[i*2]   - m)*rs*__ldg(&nw[k])   + __ldg(&nb[k]);
                float v1 = (v[i*2+1] - m)*rs*__ldg(&nw[k+1]) + __ldg(&nb[k+1]);
                __half h0 = __float2half_rn(v0);
                __half h1 = __float2half_rn(v1);
                __half2 hh; hh.x = h0; hh.y = h1;
                __half2 ll;
                ll.x = __float2half_rn(v0 - __half2float(h0));
                ll.y = __float2half_rn(v1 - __half2float(h1));
                *(__half2*)(sm + P4_AHI + tl*PROW + k*2) = hh;
                *(__half2*)(sm + P4_ALO + tl*PROW + k*2) = ll;
            }
        }
        __syncthreads();

        // --- 5 chunks, B resident, back-to-back ---
        #pragma unroll
        for (int c = 0; c < 5; c++) {
            const uint32_t sb = base + P4_B + c*PTILE;
            float acc[2][4][4];
            #pragma unroll
            for (int mt = 0; mt < 2; mt++)
                #pragma unroll
                for (int nt = 0; nt < 4; nt++)
                    #pragma unroll
                    for (int r = 0; r < 4; r++) acc[mt][nt][r] = 0.f;

            #pragma unroll
            for (int ks = 0; ks < 8; ks++) {
                const uint32_t koff = ks*32;
                uint32_t Ah[2][4], Al[2][4];
                #pragma unroll
                for (int mt = 0; mt < 2; mt++) {
                    uint32_t r = (m_base + mt*16 + a_row)*PROW + koff + a_half*16;
                    ldsm4(Ah[mt], base + P4_AHI + r);
                    ldsm4(Al[mt], base + P4_ALO + r);
                }
                uint32_t Bf[4][2];
                #pragma unroll
                for (int p = 0; p < 2; p++) {
                    uint32_t r = (n_base + p*16 + b_row)*PROW + koff + b_half*16;
                    uint32_t th[4];
                    ldsm4(th, sb + r);
                    Bf[2*p][0]   = th[0]; Bf[2*p][1]   = th[1];
                    Bf[2*p+1][0] = th[2]; Bf[2*p+1][1] = th[3];
                }
                #pragma unroll
                for (int mt = 0; mt < 2; mt++)
                    #pragma unroll
                    for (int nt = 0; nt < 4; nt++) mma16816h(acc[mt][nt], Ah[mt], Bf[nt]);
                #pragma unroll
                for (int mt = 0; mt < 2; mt++)
                    #pragma unroll
                    for (int nt = 0; nt < 4; nt++) mma16816h(acc[mt][nt], Al[mt], Bf[nt]);
            }

            if (c < 4) {
                // a/b epilogue via transpose buffer
                uint32_t* tp = (uint32_t*)(sm + P4_TP);
                const bool isA = (c < 2);
                const int cgl = (c & 1) * 64;
                #pragma unroll
                for (int mt = 0; mt < 2; mt++) {
                    #pragma unroll
                    for (int rp = 0; rp < 2; rp++) {
                        int t_loc = m_base + mt*16 + rp*8 + (lane >> 2);
                        float mk = isA ? __ldg(&mask[t0 + t_loc]) : 1.f;
                        #pragma unroll
                        for (int nt = 0; nt < 4; nt++) {
                            int c_loc = (n_base >> 1) + nt*4 + (lane & 3);
                            float val = sigmoidf_(acc[mt][nt][rp*2]) * acc[mt][nt][rp*2+1] * mk;
                            tp[c_loc*68 + t_loc] = pack_split16(val);
                        }
                    }
                }
                __syncthreads();

                #pragma unroll
                for (int rep = 0; rep < 8; rep++) {
                    int idx = tid + rep*256;        // 0..2047
                    int cl = idx >> 5, t2 = idx & 31;
                    uint32_t u0 = tp[cl*68 + t2*2];
                    uint32_t u1 = tp[cl*68 + t2*2 + 1];
                    uint32_t hi2 = (u0 & 0xFFFFu) | (u1 << 16);
                    size_t o = ((size_t)(cgl + cl)*NTOK + t0) >> 1;
                    if (isA) {
                        uint32_t lo2 = (u0 >> 16) | (u1 & 0xFFFF0000u);
                        ((uint32_t*)g_ahi)[o + t2] = hi2;
                        ((uint32_t*)g_alo)[o + t2] = lo2;
                    } else {
                        ((uint32_t*)g_bhi)[o + t2] = hi2;
                    }
                }
                __syncthreads();
            } else {
                // out-gate epilogue: token-major sigmoid, direct stores
                #pragma unroll
                for (int mt = 0; mt < 2; mt++) {
                    #pragma unroll
                    for (int rp = 0; rp < 2; rp++) {
                        int t = t0 + m_base + mt*16 + rp*8 + (lane >> 2);
                        #pragma unroll
                        for (int nt = 0; nt < 4; nt++) {
                            int ch = n_base + nt*8 + (lane & 3)*2;
                            float2 f = make_float2(sigmoidf_(acc[mt][nt][rp*2]),
                                                   sigmoidf_(acc[mt][nt][rp*2+1]));
                            *(float2*)&g_gate[(size_t)t*CCH + ch] = f;
                        }
                    }
                }
            }
        }
        __syncthreads();   // protect A region before next tile's LN writes
    }
}

// ---------------------------------------------------------------------------
// Kernel 2: tri einsum, 2-pass split-fp16, triple-buffered. (unchanged)
// ---------------------------------------------------------------------------
#define ROWB    144
#define TILEB   (128*ROWB)          // 18432
#define CHUNK3  (3*TILEB)           // 55296

__device__ __forceinline__ void tri_load_chunk(
    uint32_t sbuf, const __half* s0, const __half* s1, const __half* s2,
    int kk, int tid)
{
    const __half* srcs[3] = {s0, s1, s2};
    #pragma unroll
    for (int rep = 0; rep < 12; rep++) {
        int it   = tid + rep*256;
        int tile = it >> 10;
        int row  = (it >> 3) & 127;
        int q8   = it & 7;
        const __half* gp = srcs[tile] + (size_t)row*SDIM + kk + q8*8;
        CP_ASYNC16(sbuf + tile*TILEB + row*ROWB + q8*16, gp);
    }
}

__global__ void __launch_bounds__(256) tri_mma_kernel()
{
    extern __shared__ char dynsm[];
    const uint32_t base = smem_u32(dynsm);

    const int tid  = threadIdx.x;
    const int wid  = tid >> 5;
    const int lane = tid & 31;
    const int m_base = (wid >> 2) * 64;
    const int n_base = (wid & 3) * 32;

    const int c  = blockIdx.y;
    const int i0 = (blockIdx.x / 6) * 128;
    const int j0 = (blockIdx.x % 6) * 128;

    const __half* sAh = g_ahi + (size_t)c*NTOK + (size_t)i0*SDIM;
    const __half* sAl = g_alo + (size_t)c*NTOK + (size_t)i0*SDIM;
    const __half* sBh = g_bhi + (size_t)c*NTOK + (size_t)j0*SDIM;

    float acc[4][4][4];
    #pragma unroll
    for (int mt = 0; mt < 4; mt++)
        #pragma unroll
        for (int nt = 0; nt < 4; nt++)
            #pragma unroll
            for (int r = 0; r < 4; r++) acc[mt][nt][r] = 0.f;

    const int a_row  = lane & 15;
    const int a_half = lane >> 4;
    const int b_quad = lane >> 3;
    const int b_row  = (b_quad >> 1) * 8 + (lane & 7);
    const int b_half = b_quad & 1;

    tri_load_chunk(base + 0*CHUNK3, sAh, sAl, sBh, 0,  tid); CP_COMMIT();
    tri_load_chunk(base + 1*CHUNK3, sAh, sAl, sBh, 64, tid); CP_COMMIT();

    for (int n = 0; n < 12; n++) {
        if (n + 2 < 12)
            tri_load_chunk(base + ((n+2)%3)*CHUNK3, sAh, sAl, sBh, (n+2)*64, tid);
        CP_COMMIT();
        CP_WAIT2();
        __syncthreads();

        const uint32_t sb = base + (n%3)*CHUNK3;
        #pragma unroll
        for (int ks = 0; ks < 4; ks++) {
            uint32_t Ah[4][4], Al[4][4], Bh[4][2];
            const uint32_t koff = ks*32;
            #pragma unroll
            for (int mt = 0; mt < 4; mt++) {
                uint32_t r = (m_base + mt*16 + a_row)*ROWB + koff + a_half*16;
                ldsm4(Ah[mt], sb + 0*TILEB + r);
                ldsm4(Al[mt], sb + 1*TILEB + r);
            }
            #pragma unroll
            for (int p = 0; p < 2; p++) {
                uint32_t r = (n_base + p*16 + b_row)*ROWB + koff + b_half*16;
                uint32_t th[4];
                ldsm4(th, sb + 2*TILEB + r);
                Bh[2*p][0]   = th[0]; Bh[2*p][1]   = th[1];
                Bh[2*p+1][0] = th[2]; Bh[2*p+1][1] = th[3];
            }
            #pragma unroll
            for (int mt = 0; mt < 4; mt++)
                #pragma unroll
                for (int nt = 0; nt < 4; nt++)
                    mma16816h(acc[mt][nt], Ah[mt], Bh[nt]);
            #pragma unroll
            for (int mt = 0; mt < 4; mt++)
                #pragma unroll
                for (int nt = 0; nt < 4; nt++)
                    mma16816h(acc[mt][nt], Al[mt], Bh[nt]);
        }
        __syncthreads();
    }

    float* T = g_tri + (size_t)c*NTOK;
    const int er = i0 + m_base + (lane >> 2);
    const int ec2 = j0 + n_base + (lane & 3)*2;
    #pragma unroll
    for (int mt = 0; mt < 4; mt++) {
        #pragma unroll
        for (int nt = 0; nt < 4; nt++) {
            int rr = er + mt*16;
            int cc = ec2 + nt*8;
            *(float2*)&T[(size_t)rr*SDIM + cc]     = make_float2(acc[mt][nt][0], acc[mt][nt][1]);
            *(float2*)&T[(size_t)(rr+8)*SDIM + cc] = make_float2(acc[mt][nt][2], acc[mt][nt][3]);
        }
    }
}

// ---------------------------------------------------------------------------
// Kernel 3: out512 — persistent, 512 threads, 128-token tiles, B resident,
// tri staged (prefetch after LN), gate read by direct LDG.
// ---------------------------------------------------------------------------
#define OT_TRI   0                      // 128 ch x 528B (f32 [ch][t], 132-stride)
#define OT_AHI   67584                  // 128 x 272B
#define OT_ALO   (OT_AHI + PTILE)
#define OT_B     (OT_ALO + PTILE)       // 34816
#define OT_SMEM  (OT_B + PTILE)         // 172032
#define NOT128   (NTOK/128)             // 4608

__global__ void __launch_bounds__(512) out512_kernel(
    const float* __restrict__ now, const float* __restrict__ nob,
    float* __restrict__ out)
{
    extern __shared__ char sm[];
    const uint32_t base = smem_u32(sm);
    const int tid = threadIdx.x;
    const int bid = blockIdx.x;

    // one-time B (wpo^T fp16 hi)
    #pragma unroll
    for (int rep = 0; rep < 4; rep++) {
        int it = tid + rep*512;
        int row = it >> 4, q = it & 15;
        CP_ASYNC16(base + OT_B + row*PROW + q*16,
                   (const char*)(g_wpo16 + row*128) + q*16);
    }
    // first tri tile
    {
        int t0 = bid * 128;
        #pragma unroll
        for (int rep = 0; rep < 8; rep++) {
            int it = tid + rep*512;           // 0..4095
            int ch = it >> 5, q = it & 31;
            CP_ASYNC16(base + OT_TRI + ch*528 + q*16,
                       g_tri + (size_t)ch*NTOK + t0 + q*4);
        }
    }
    CP_COMMIT();

    const int wid  = tid >> 5;
    const int lane = tid & 31;
    const int m_base = (wid >> 2) * 32;   // 4 m-warps over 128 tokens
    const int n_base = (wid & 3) * 32;
    const int a_row  = lane & 15;
    const int a_half = lane >> 4;
    const int b_quad = lane >> 3;
    const int b_row  = (b_quad >> 1)*8 + (lane & 7);
    const int b_half = b_quad & 1;
    const int er = m_base + (lane >> 2);
    const int ec = n_base + (lane & 3)*2;

    const float* trs = (const float*)(sm + OT_TRI);
    const int tl = tid >> 2, qq = tid & 3;    // LN: 4 threads per token (128 tok)

    for (int tile = bid; tile < NOT128; tile += NSM) {
        const int t0 = tile * 128;
        CP_WAIT0();
        __syncthreads();

        // LN over channels -> split fp16 A [t][ch]
        {
            float s = 0.f;
            #pragma unroll 8
            for (int j = 0; j < 32; j++) s += trs[(qq*32 + j)*132 + tl];
            s += __shfl_xor_sync(0xFFFFFFFFu, s, 1);
            s += __shfl_xor_sync(0xFFFFFFFFu, s, 2);
            float m = s * (1.f/128.f);
            float q2 = 0.f;
            #pragma unroll 8
            for (int j = 0; j < 32; j++) {
                float d = trs[(qq*32 + j)*132 + tl] - m;
                q2 += d*d;
            }
            q2 += __shfl_xor_sync(0xFFFFFFFFu, q2, 1);
            q2 += __shfl_xor_sync(0xFFFFFFFFu, q2, 2);
            float rs = rsqrtf(q2 * (1.f/128.f) + 1e-5f);

            #pragma unroll
            for (int j = 0; j < 16; j++) {
                int ch = qq*32 + j*2;
                float v0 = (trs[ch*132 + tl]     - m)*rs*__ldg(&now[ch])   + __ldg(&nob[ch]);
                float v1 = (trs[(ch+1)*132 + tl] - m)*rs*__ldg(&now[ch+1]) + __ldg(&nob[ch+1]);
                __half h0 = __float2half_rn(v0);
                __half h1 = __float2half_rn(v1);
                __half2 hh; hh.x = h0; hh.y = h1;
                __half2 ll;
                ll.x = __float2half_rn(v0 - __half2float(h0));
                ll.y = __float2half_rn(v1 - __half2float(h1));
                *(__half2*)(sm + OT_AHI + tl*PROW + ch*2) = hh;
                *(__half2*)(sm + OT_ALO + tl*PROW + ch*2) = ll;
            }
        }
        __syncthreads();

        // prefetch next tri tile into staging (LN consumed it)
        if (tile + NSM < NOT128) {
            int nt0 = (tile + NSM) * 128;
            #pragma unroll
            for (int rep = 0; rep < 8; rep++) {
                int it = tid + rep*512;
                int ch = it >> 5, q = it & 31;
                CP_ASYNC16(base + OT_TRI + ch*528 + q*16,
                           g_tri + (size_t)ch*NTOK + nt0 + q*4);
            }
        }
        CP_COMMIT();

        float acc[2][4][4];
        #pragma unroll
        for (int mt = 0; mt < 2; mt++)
            #pragma unroll
            for (int nt = 0; nt < 4; nt++)
                #pragma unroll
                for (int r = 0; r < 4; r++) acc[mt][nt][r] = 0.f;

        #pragma unroll
        for (int ks = 0; ks < 8; ks++) {
            const uint32_t koff = ks*32;
            uint32_t Ah[2][4], Al[2][4];
            #pragma unroll
            for (int mt = 0; mt < 2; mt++) {
                uint32_t r = (m_base + mt*16 + a_row)*PROW + koff + a_half*16;
                ldsm4(Ah[mt], base + OT_AHI + r);
                ldsm4(Al[mt], base + OT_ALO + r);
            }
            uint32_t Bf[4][2];
            #pragma unroll
            for (int p = 0; p < 2; p++) {
                uint32_t r = (n_base + p*16 + b_row)*PROW + koff + b_half*16;
                uint32_t th[4];
                ldsm4(th, base + OT_B + r);
                Bf[2*p][0]   = th[0]; Bf[2*p][1]   = th[1];
                Bf[2*p+1][0] = th[2]; Bf[2*p+1][1] = th[3];
            }
            #pragma unroll
            for (int mt = 0; mt < 2; mt++)
                #pragma unroll
                for (int nt = 0; nt < 4; nt++) mma16816h(acc[mt][nt], Ah[mt], Bf[nt]);
            #pragma unroll
            for (int mt = 0; mt < 2; mt++)
                #pragma unroll
                for (int nt = 0; nt < 4; nt++) mma16816h(acc[mt][nt], Al[mt], Bf[nt]);
        }

        // epilogue: gate via direct LDG, out stores
        #pragma unroll
        for (int mt = 0; mt < 2; mt++) {
            #pragma unroll
            for (int rp = 0; rp < 2; rp++) {
                int t = t0 + er + mt*16 + rp*8;
                #pragma unroll
                for (int nt = 0; nt < 4; nt++) {
                    int cc = ec + nt*8;
                    float2 gg = __ldg((const float2*)&g_gate[(size_t)t*CCH + cc]);
                    float2 o = make_float2(acc[mt][nt][rp*2]   * gg.x,
                                           acc[mt][nt][rp*2+1] * gg.y);
                    *(float2*)&out[(size_t)t*CCH + cc] = o;
                }
            }
        }
        __syncthreads();   // protect A/staging before next iteration
    }
}

// ---------------------------------------------------------------------------
extern "C" void kernel_launch(void* const* d_in, const int* in_sizes, int n_in,
                              void* d_out, int out_size)
{
    const float* x    = (const float*)d_in[0];
    const float* mask = (const float*)d_in[1];
    const float* niw  = (const float*)d_in[2];
    const float* nib  = (const float*)d_in[3];
    const float* wgi  = (const float*)d_in[4];
    const float* wpi  = (const float*)d_in[5];
    const float* now  = (const float*)d_in[6];
    const float* nob  = (const float*)d_in[7];
    const float* wgo  = (const float*)d_in[8];
    const float* wpo  = (const float*)d_in[9];
    float* out = (float*)d_out;

    cudaFuncSetAttribute(proj4_kernel,
        cudaFuncAttributeMaxDynamicSharedMemorySize, P4_SMEM);
    cudaFuncSetAttribute(tri_mma_kernel,
        cudaFuncAttributeMaxDynamicSharedMemorySize, 3*CHUNK3);
    cudaFuncSetAttribute(out512_kernel,
        cudaFuncAttributeMaxDynamicSharedMemorySize, OT_SMEM);

    prep_w_kernel<<<256, 256>>>(wgi, wpi, wgo, wpo);
    proj4_kernel<<<NSM, 256, P4_SMEM>>>(x, mask, niw, nib);
    tri_mma_kernel<<<dim3(36, 128), 256, 3*CHUNK3>>>();
    out512_kernel<<<NSM, 512, OT_SMEM>>>(now, nob, out);
}

// round 10
// speedup vs baseline: 1.3729x; 1.1868x over previous
#include <cuda_runtime.h>
#include <cuda_bf16.h>
#include <cuda_fp16.h>
#include <math.h>
#include <stdint.h>

#define SDIM 768
#define CCH  128
#define NTOK (SDIM*SDIM)        // 589824 tokens
#define SELEM 75497472          // 128 * 589824
#define NSM   148

// Scratch: a, b as fp16 hi only; tri fp32; gate fp16
__device__ __half g_ahi[SELEM];
__device__ __half g_bhi[SELEM];
__device__ float g_tri[SELEM];
__device__ __half g_gate16[SELEM];

// Prepped fp16 weights:
// g_wcI: 4 groups x 128 rows x 128 k; group g row 2r = wgi col(64g+r), row 2r+1 = wpi col(64g+r)
__device__ __half g_wcI[4*128*128];
__device__ __half g_wgo16[128*128];   // wgo^T [n][k]
__device__ __half g_wpo16[128*128];   // wpo^T [co][h]

__device__ __forceinline__ float sigmoidf_(float v) {
    return 1.f / (1.f + __expf(-v));
}
__device__ __forceinline__ uint32_t smem_u32(const void* p) {
    uint32_t a;
    asm("{ .reg .u64 t; cvta.to.shared.u64 t, %1; cvt.u32.u64 %0, t; }"
        : "=r"(a) : "l"(p));
    return a;
}
#define CP_ASYNC16(d, s)  asm volatile("cp.async.cg.shared.global [%0], [%1], 16;" :: "r"(d), "l"(s))
#define CP_COMMIT()       asm volatile("cp.async.commit_group;" ::: "memory")
#define CP_WAIT0()        asm volatile("cp.async.wait_group 0;" ::: "memory")
#define CP_WAIT2()        asm volatile("cp.async.wait_group 2;" ::: "memory")

__device__ __forceinline__ void ldsm4(uint32_t* r, uint32_t addr) {
    asm volatile("ldmatrix.sync.aligned.m8n8.x4.shared.b16 {%0,%1,%2,%3}, [%4];"
        : "=r"(r[0]), "=r"(r[1]), "=r"(r[2]), "=r"(r[3]) : "r"(addr));
}
__device__ __forceinline__ void mma16816h(float* d, const uint32_t* a, const uint32_t* b) {
    asm volatile("mma.sync.aligned.m16n8k16.row.col.f32.f16.f16.f32 "
        "{%0,%1,%2,%3}, {%4,%5,%6,%7}, {%8,%9}, {%0,%1,%2,%3};"
        : "+f"(d[0]), "+f"(d[1]), "+f"(d[2]), "+f"(d[3])
        : "r"(a[0]), "r"(a[1]), "r"(a[2]), "r"(a[3]), "r"(b[0]), "r"(b[1]));
}

// ---------------------------------------------------------------------------
// Kernel 0: weight prep.
// ---------------------------------------------------------------------------
__global__ void __launch_bounds__(256) prep_w_kernel(
    const float* __restrict__ wgi, const float* __restrict__ wpi,
    const float* __restrict__ wgo, const float* __restrict__ wpo)
{
    int idx = blockIdx.x*256 + threadIdx.x;   // 0..65535
    {
        int g = idx >> 14, rem = idx & 16383;
        int row = rem >> 7, k = rem & 127;
        int col = g*64 + (row >> 1);
        float v = (row & 1) ? wpi[k*256 + col] : wgi[k*256 + col];
        g_wcI[idx] = __float2half_rn(v);
    }
    if (idx < 16384) {
        int n = idx >> 7, k = idx & 127;
        g_wgo16[idx] = __float2half_rn(wgo[k*128 + n]);
        g_wpo16[idx] = __float2half_rn(wpo[k*128 + n]);
    }
}

// ---------------------------------------------------------------------------
// Kernel 1: proj4 — persistent; 64-token tiles; 5 weight chunks smem-resident.
// LN(x) split hi/lo (exact), 2-pass HMMA; outputs a/b as fp16-hi; gate fp16.
// ---------------------------------------------------------------------------
#define PROW   272
#define PTILE  (128*PROW)         // 34816
#define ATILE  (64*PROW)          // 17408
#define P4_AHI  0
#define P4_ALO  ATILE                      // 17408
#define P4_B    (2*ATILE)                  // 34816
#define P4_TP   (P4_B + 5*PTILE)           // 208896
#define P4_SMEM (P4_TP + 64*68*4)          // 226304
#define NP4     (NTOK/64)                  // 9216

__global__ void __launch_bounds__(256) proj4_kernel(
    const float* __restrict__ x, const float* __restrict__ mask,
    const float* __restrict__ nw, const float* __restrict__ nb)
{
    extern __shared__ char sm[];
    const uint32_t base = smem_u32(sm);
    const int tid = threadIdx.x;
    const int bid = blockIdx.x;

    const int wid  = tid >> 5;
    const int lane = tid & 31;
    const int m_base = (wid >> 2) * 32;
    const int n_base = (wid & 3) * 32;
    const int a_row  = lane & 15;
    const int a_half = lane >> 4;
    const int b_quad = lane >> 3;
    const int b_row  = (b_quad >> 1)*8 + (lane & 7);
    const int b_half = b_quad & 1;

    // --- load ALL 5 B chunks once ---
    const __half* csrc[5] = { g_wcI, g_wcI + 16384, g_wcI + 32768,
                              g_wcI + 49152, g_wgo16 };
    for (int cc = 0; cc < 5; cc++) {
        const __half* s = csrc[cc];
        uint32_t dst = base + P4_B + cc*PTILE;
        #pragma unroll
        for (int rep = 0; rep < 8; rep++) {
            int it = tid + rep*256;
            int row = it >> 4, q = it & 15;
            CP_ASYNC16(dst + row*PROW + q*16, (const char*)(s + row*128) + q*16);
        }
    }
    CP_COMMIT();
    CP_WAIT0();
    __syncthreads();

    const int tl = tid >> 2, qq = tid & 3;    // LN: 4 threads per token

    for (int tile = bid; tile < NP4; tile += NSM) {
        const int t0 = tile * 64;

        // --- LN(x) direct from gmem -> split fp16 A (hi/lo exact) ---
        {
            const float* xrow = x + (size_t)(t0 + tl)*CCH + qq*32;
            float v[32];
            float s = 0.f;
            #pragma unroll
            for (int i = 0; i < 8; i++) {
                float4 f = __ldg((const float4*)(xrow + i*4));
                v[i*4]=f.x; v[i*4+1]=f.y; v[i*4+2]=f.z; v[i*4+3]=f.w;
                s += f.x + f.y + f.z + f.w;
            }
            s += __shfl_xor_sync(0xFFFFFFFFu, s, 1);
            s += __shfl_xor_sync(0xFFFFFFFFu, s, 2);
            float m = s * (1.f/128.f);
            float q2 = 0.f;
            #pragma unroll
            for (int i = 0; i < 32; i++) { float d = v[i]-m; q2 += d*d; }
            q2 += __shfl_xor_sync(0xFFFFFFFFu, q2, 1);
            q2 += __shfl_xor_sync(0xFFFFFFFFu, q2, 2);
            float rs = rsqrtf(q2 * (1.f/128.f) + 1e-5f);

            #pragma unroll
            for (int i = 0; i < 16; i++) {
                int k = qq*32 + i*2;
                float v0 = (v[i*2]   - m)*rs*__ldg(&nw[k])   + __ldg(&nb[k]);
                float v1 = (v[i*2+1] - m)*rs*__ldg(&nw[k+1]) + __ldg(&nb[k+1]);
                __half h0 = __float2half_rn(v0);
                __half h1 = __float2half_rn(v1);
                __half2 hh; hh.x = h0; hh.y = h1;
                __half2 ll;
                ll.x = __float2half_rn(v0 - __half2float(h0));
                ll.y = __float2half_rn(v1 - __half2float(h1));
                *(__half2*)(sm + P4_AHI + tl*PROW + k*2) = hh;
                *(__half2*)(sm + P4_ALO + tl*PROW + k*2) = ll;
            }
        }
        __syncthreads();

        // --- 5 chunks, B resident, back-to-back ---
        #pragma unroll
        for (int c = 0; c < 5; c++) {
            const uint32_t sb = base + P4_B + c*PTILE;
            float acc[2][4][4];
            #pragma unroll
            for (int mt = 0; mt < 2; mt++)
                #pragma unroll
                for (int nt = 0; nt < 4; nt++)
                    #pragma unroll
                    for (int r = 0; r < 4; r++) acc[mt][nt][r] = 0.f;

            #pragma unroll
            for (int ks = 0; ks < 8; ks++) {
                const uint32_t koff = ks*32;
                uint32_t Ah[2][4], Al[2][4];
                #pragma unroll
                for (int mt = 0; mt < 2; mt++) {
                    uint32_t r = (m_base + mt*16 + a_row)*PROW + koff + a_half*16;
                    ldsm4(Ah[mt], base + P4_AHI + r);
                    ldsm4(Al[mt], base + P4_ALO + r);
                }
                uint32_t Bf[4][2];
                #pragma unroll
                for (int p = 0; p < 2; p++) {
                    uint32_t r = (n_base + p*16 + b_row)*PROW + koff + b_half*16;
                    uint32_t th[4];
                    ldsm4(th, sb + r);
                    Bf[2*p][0]   = th[0]; Bf[2*p][1]   = th[1];
                    Bf[2*p+1][0] = th[2]; Bf[2*p+1][1] = th[3];
                }
                #pragma unroll
                for (int mt = 0; mt < 2; mt++)
                    #pragma unroll
                    for (int nt = 0; nt < 4; nt++) mma16816h(acc[mt][nt], Ah[mt], Bf[nt]);
                #pragma unroll
                for (int mt = 0; mt < 2; mt++)
                    #pragma unroll
                    for (int nt = 0; nt < 4; nt++) mma16816h(acc[mt][nt], Al[mt], Bf[nt]);
            }

            if (c < 4) {
                // a/b epilogue: hi-only via transpose buffer
                uint32_t* tp = (uint32_t*)(sm + P4_TP);
                const bool isA = (c < 2);
                const int cgl = (c & 1) * 64;
                #pragma unroll
                for (int mt = 0; mt < 2; mt++) {
                    #pragma unroll
                    for (int rp = 0; rp < 2; rp++) {
                        int t_loc = m_base + mt*16 + rp*8 + (lane >> 2);
                        float mk = isA ? __ldg(&mask[t0 + t_loc]) : 1.f;
                        #pragma unroll
                        for (int nt = 0; nt < 4; nt++) {
                            int c_loc = (n_base >> 1) + nt*4 + (lane & 3);
                            float val = sigmoidf_(acc[mt][nt][rp*2]) * acc[mt][nt][rp*2+1] * mk;
                            tp[c_loc*68 + t_loc] =
                                (uint32_t)__half_as_ushort(__float2half_rn(val));
                        }
                    }
                }
                __syncthreads();

                #pragma unroll
                for (int rep = 0; rep < 8; rep++) {
                    int idx = tid + rep*256;        // 0..2047
                    int cl = idx >> 5, t2 = idx & 31;
                    uint32_t u0 = tp[cl*68 + t2*2];
                    uint32_t u1 = tp[cl*68 + t2*2 + 1];
                    uint32_t hi2 = (u0 & 0xFFFFu) | (u1 << 16);
                    size_t o = ((size_t)(cgl + cl)*NTOK + t0) >> 1;
                    if (isA) ((uint32_t*)g_ahi)[o + t2] = hi2;
                    else     ((uint32_t*)g_bhi)[o + t2] = hi2;
                }
                __syncthreads();
            } else {
                // out-gate epilogue: token-major sigmoid -> fp16
                #pragma unroll
                for (int mt = 0; mt < 2; mt++) {
                    #pragma unroll
                    for (int rp = 0; rp < 2; rp++) {
                        int t = t0 + m_base + mt*16 + rp*8 + (lane >> 2);
                        #pragma unroll
                        for (int nt = 0; nt < 4; nt++) {
                            int ch = n_base + nt*8 + (lane & 3)*2;
                            __half2 f;
                            f.x = __float2half_rn(sigmoidf_(acc[mt][nt][rp*2]));
                            f.y = __float2half_rn(sigmoidf_(acc[mt][nt][rp*2+1]));
                            *(__half2*)&g_gate16[(size_t)t*CCH + ch] = f;
                        }
                    }
                }
            }
        }
        __syncthreads();
    }
}

// ---------------------------------------------------------------------------
// Kernel 2: tri einsum, SINGLE-pass fp16 (a_hi · b_hi), K-chunk=128, triple buf.
// ---------------------------------------------------------------------------
#define TILE2   (128*PROW)          // 34816 (128 rows x 256B data + pad)
#define CHUNKT  (2*TILE2)           // 69632
#define TRI_SMEM (3*CHUNKT)         // 208896

__device__ __forceinline__ void tri_load_chunk(
    uint32_t sbuf, const __half* sA, const __half* sB, int kk, int tid)
{
    const __half* srcs[2] = {sA, sB};
    #pragma unroll
    for (int rep = 0; rep < 16; rep++) {
        int it   = tid + rep*256;             // 0..4095
        int tile = it >> 11;
        int row  = (it >> 4) & 127;
        int q    = it & 15;
        const __half* gp = srcs[tile] + (size_t)row*SDIM + kk + q*8;
        CP_ASYNC16(sbuf + tile*TILE2 + row*PROW + q*16, gp);
    }
}

__global__ void __launch_bounds__(256) tri_mma_kernel()
{
    extern __shared__ char dynsm[];
    const uint32_t base = smem_u32(dynsm);

    const int tid  = threadIdx.x;
    const int wid  = tid >> 5;
    const int lane = tid & 31;
    const int m_base = (wid >> 2) * 64;
    const int n_base = (wid & 3) * 32;

    const int c  = blockIdx.y;
    const int i0 = (blockIdx.x / 6) * 128;
    const int j0 = (blockIdx.x % 6) * 128;

    const __half* sAh = g_ahi + (size_t)c*NTOK + (size_t)i0*SDIM;
    const __half* sBh = g_bhi + (size_t)c*NTOK + (size_t)j0*SDIM;

    float acc[4][4][4];
    #pragma unroll
    for (int mt = 0; mt < 4; mt++)
        #pragma unroll
        for (int nt = 0; nt < 4; nt++)
            #pragma unroll
            for (int r = 0; r < 4; r++) acc[mt][nt][r] = 0.f;

    const int a_row  = lane & 15;
    const int a_half = lane >> 4;
    const int b_quad = lane >> 3;
    const int b_row  = (b_quad >> 1) * 8 + (lane & 7);
    const int b_half = b_quad & 1;

    tri_load_chunk(base + 0*CHUNKT, sAh, sBh, 0,   tid); CP_COMMIT();
    tri_load_chunk(base + 1*CHUNKT, sAh, sBh, 128, tid); CP_COMMIT();

    for (int n = 0; n < 6; n++) {
        if (n + 2 < 6)
            tri_load_chunk(base + ((n+2)%3)*CHUNKT, sAh, sBh, (n+2)*128, tid);
        CP_COMMIT();
        CP_WAIT2();
        __syncthreads();

        const uint32_t sb = base + (n%3)*CHUNKT;
        #pragma unroll
        for (int ks = 0; ks < 8; ks++) {
            uint32_t Ah[4][4], Bh[4][2];
            const uint32_t koff = ks*32;
            #pragma unroll
            for (int mt = 0; mt < 4; mt++) {
                uint32_t r = (m_base + mt*16 + a_row)*PROW + koff + a_half*16;
                ldsm4(Ah[mt], sb + r);
            }
            #pragma unroll
            for (int p = 0; p < 2; p++) {
                uint32_t r = (n_base + p*16 + b_row)*PROW + koff + b_half*16;
                uint32_t th[4];
                ldsm4(th, sb + TILE2 + r);
                Bh[2*p][0]   = th[0]; Bh[2*p][1]   = th[1];
                Bh[2*p+1][0] = th[2]; Bh[2*p+1][1] = th[3];
            }
            #pragma unroll
            for (int mt = 0; mt < 4; mt++)
                #pragma unroll
                for (int nt = 0; nt < 4; nt++)
                    mma16816h(acc[mt][nt], Ah[mt], Bh[nt]);
        }
        __syncthreads();
    }

    float* T = g_tri + (size_t)c*NTOK;
    const int er = i0 + m_base + (lane >> 2);
    const int ec2 = j0 + n_base + (lane & 3)*2;
    #pragma unroll
    for (int mt = 0; mt < 4; mt++) {
        #pragma unroll
        for (int nt = 0; nt < 4; nt++) {
            int rr = er + mt*16;
            int cc = ec2 + nt*8;
            *(float2*)&T[(size_t)rr*SDIM + cc]     = make_float2(acc[mt][nt][0], acc[mt][nt][1]);
            *(float2*)&T[(size_t)(rr+8)*SDIM + cc] = make_float2(acc[mt][nt][2], acc[mt][nt][3]);
        }
    }
}

// ---------------------------------------------------------------------------
// Kernel 3: out512 — 512 threads, 128-token tiles, single-pass fp16,
// gate fp16 via direct LDG.
// ---------------------------------------------------------------------------
#define OT_TRI   0                      // 128 ch x 528B (f32 [ch][t], 132-stride)
#define OT_AHI   67584                  // 128 x 272B
#define OT_B     (OT_AHI + PTILE)       // 34816
#define OT_SMEM  (OT_B + PTILE)         // 137216
#define NOT128   (NTOK/128)             // 4608

__global__ void __launch_bounds__(512) out512_kernel(
    const float* __restrict__ now, const float* __restrict__ nob,
    float* __restrict__ out)
{
    extern __shared__ char sm[];
    const uint32_t base = smem_u32(sm);
    const int tid = threadIdx.x;
    const int bid = blockIdx.x;

    // one-time B (wpo^T fp16 hi)
    #pragma unroll
    for (int rep = 0; rep < 4; rep++) {
        int it = tid + rep*512;
        int row = it >> 4, q = it & 15;
        CP_ASYNC16(base + OT_B + row*PROW + q*16,
                   (const char*)(g_wpo16 + row*128) + q*16);
    }
    // first tri tile
    {
        int t0 = bid * 128;
        #pragma unroll
        for (int rep = 0; rep < 8; rep++) {
            int it = tid + rep*512;           // 0..4095
            int ch = it >> 5, q = it & 31;
            CP_ASYNC16(base + OT_TRI + ch*528 + q*16,
                       g_tri + (size_t)ch*NTOK + t0 + q*4);
        }
    }
    CP_COMMIT();

    const int wid  = tid >> 5;
    const int lane = tid & 31;
    const int m_base = (wid >> 2) * 32;   // 4 m-warps over 128 tokens
    const int n_base = (wid & 3) * 32;
    const int a_row  = lane & 15;
    const int a_half = lane >> 4;
    const int b_quad = lane >> 3;
    const int b_row  = (b_quad >> 1)*8 + (lane & 7);
    const int b_half = b_quad & 1;
    const int er = m_base + (lane >> 2);
    const int ec = n_base + (lane & 3)*2;

    const float* trs = (const float*)(sm + OT_TRI);
    const int tl = tid >> 2, qq = tid & 3;

    for (int tile = bid; tile < NOT128; tile += NSM) {
        const int t0 = tile * 128;
        CP_WAIT0();
        __syncthreads();

        // LN over channels -> fp16 A [t][ch] (hi only)
        {
            float s = 0.f;
            #pragma unroll 8
            for (int j = 0; j < 32; j++) s += trs[(qq*32 + j)*132 + tl];
            s += __shfl_xor_sync(0xFFFFFFFFu, s, 1);
            s += __shfl_xor_sync(0xFFFFFFFFu, s, 2);
            float m = s * (1.f/128.f);
            float q2 = 0.f;
            #pragma unroll 8
            for (int j = 0; j < 32; j++) {
                float d = trs[(qq*32 + j)*132 + tl] - m;
                q2 += d*d;
            }
            q2 += __shfl_xor_sync(0xFFFFFFFFu, q2, 1);
            q2 += __shfl_xor_sync(0xFFFFFFFFu, q2, 2);
            float rs = rsqrtf(q2 * (1.f/128.f) + 1e-5f);

            #pragma unroll
            for (int j = 0; j < 16; j++) {
                int ch = qq*32 + j*2;
                float v0 = (trs[ch*132 + tl]     - m)*rs*__ldg(&now[ch])   + __ldg(&nob[ch]);
                float v1 = (trs[(ch+1)*132 + tl] - m)*rs*__ldg(&now[ch+1]) + __ldg(&nob[ch+1]);
                __half2 hh;
                hh.x = __float2half_rn(v0);
                hh.y = __float2half_rn(v1);
                *(__half2*)(sm + OT_AHI + tl*PROW + ch*2) = hh;
            }
        }
        __syncthreads();

        // prefetch next tri tile into staging (LN consumed it)
        if (tile + NSM < NOT128) {
            int nt0 = (tile + NSM) * 128;
            #pragma unroll
            for (int rep = 0; rep < 8; rep++) {
                int it = tid + rep*512;
                int ch = it >> 5, q = it & 31;
                CP_ASYNC16(base + OT_TRI + ch*528 + q*16,
                           g_tri + (size_t)ch*NTOK + nt0 + q*4);
            }
        }
        CP_COMMIT();

        float acc[2][4][4];
        #pragma unroll
        for (int mt = 0; mt < 2; mt++)
            #pragma unroll
            for (int nt = 0; nt < 4; nt++)
                #pragma unroll
                for (int r = 0; r < 4; r++) acc[mt][nt][r] = 0.f;

        #pragma unroll
        for (int ks = 0; ks < 8; ks++) {
            const uint32_t koff = ks*32;
            uint32_t Ah[2][4];
            #pragma unroll
            for (int mt = 0; mt < 2; mt++) {
                uint32_t r = (m_base + mt*16 + a_row)*PROW + koff + a_half*16;
                ldsm4(Ah[mt], base + OT_AHI + r);
            }
            uint32_t Bf[4][2];
            #pragma unroll
            for (int p = 0; p < 2; p++) {
                uint32_t r = (n_base + p*16 + b_row)*PROW + koff + b_half*16;
                uint32_t th[4];
                ldsm4(th, base + OT_B + r);
                Bf[2*p][0]   = th[0]; Bf[2*p][1]   = th[1];
                Bf[2*p+1][0] = th[2]; Bf[2*p+1][1] = th[3];
            }
            #pragma unroll
            for (int mt = 0; mt < 2; mt++)
                #pragma unroll
                for (int nt = 0; nt < 4; nt++) mma16816h(acc[mt][nt], Ah[mt], Bf[nt]);
        }

        // epilogue: gate fp16 via direct LDG, out stores
        #pragma unroll
        for (int mt = 0; mt < 2; mt++) {
            #pragma unroll
            for (int rp = 0; rp < 2; rp++) {
                int t = t0 + er + mt*16 + rp*8;
                #pragma unroll
                for (int nt = 0; nt < 4; nt++) {
                    int cc = ec + nt*8;
                    __half2 gh = __ldg((const __half2*)&g_gate16[(size_t)t*CCH + cc]);
                    float2 o = make_float2(acc[mt][nt][rp*2]   * __half2float(gh.x),
                                           acc[mt][nt][rp*2+1] * __half2float(gh.y));
                    *(float2*)&out[(size_t)t*CCH + cc] = o;
                }
            }
        }
        __syncthreads();
    }
}

// ---------------------------------------------------------------------------
extern "C" void kernel_launch(void* const* d_in, const int* in_sizes, int n_in,
                              void* d_out, int out_size)
{
    const float* x    = (const float*)d_in[0];
    const float* mask = (const float*)d_in[1];
    const float* niw  = (const float*)d_in[2];
    const float* nib  = (const float*)d_in[3];
    const float* wgi  = (const float*)d_in[4];
    const float* wpi  = (const float*)d_in[5];
    const float* now  = (const float*)d_in[6];
    const float* nob  = (const float*)d_in[7];
    const float* wgo  = (const float*)d_in[8];
    const float* wpo  = (const float*)d_in[9];
    float* out = (float*)d_out;

    cudaFuncSetAttribute(proj4_kernel,
        cudaFuncAttributeMaxDynamicSharedMemorySize, P4_SMEM);
    cudaFuncSetAttribute(tri_mma_kernel,
        cudaFuncAttributeMaxDynamicSharedMemorySize, TRI_SMEM);
    cudaFuncSetAttribute(out512_kernel,
        cudaFuncAttributeMaxDynamicSharedMemorySize, OT_SMEM);

    prep_w_kernel<<<256, 256>>>(wgi, wpi, wgo, wpo);
    proj4_kernel<<<NSM, 256, P4_SMEM>>>(x, mask, niw, nib);
    tri_mma_kernel<<<dim3(36, 128), 256, TRI_SMEM>>>();
    out512_kernel<<<NSM, 512, OT_SMEM>>>(now, nob, out);
}

// round 11
// speedup vs baseline: 1.6928x; 1.2329x over previous
#include <cuda_runtime.h>
#include <cuda_bf16.h>
#include <cuda_fp16.h>
#include <math.h>
#include <stdint.h>

#define SDIM 768
#define CCH  128
#define NTOK (SDIM*SDIM)        // 589824 tokens
#define SELEM 75497472          // 128 * 589824
#define NSM   148

// Scratch: a, b, tri, gate all fp16
__device__ __half g_ahi[SELEM];
__device__ __half g_bhi[SELEM];
__device__ __half g_tri16[SELEM];
__device__ __half g_gate16[SELEM];

// Prepped fp16 weights:
// g_wcI: 4 groups x 128 rows x 128 k; group g row 2r = wgi col(64g+r), row 2r+1 = wpi col(64g+r)
__device__ __half g_wcI[4*128*128];
__device__ __half g_wgo16[128*128];   // wgo^T [n][k]
__device__ __half g_wpo16[128*128];   // wpo^T [co][h]

__device__ __forceinline__ float sigmoidf_(float v) {
    return 1.f / (1.f + __expf(-v));
}
__device__ __forceinline__ uint32_t smem_u32(const void* p) {
    uint32_t a;
    asm("{ .reg .u64 t; cvta.to.shared.u64 t, %1; cvt.u32.u64 %0, t; }"
        : "=r"(a) : "l"(p));
    return a;
}
#define CP_ASYNC16(d, s)  asm volatile("cp.async.cg.shared.global [%0], [%1], 16;" :: "r"(d), "l"(s))
#define CP_COMMIT()       asm volatile("cp.async.commit_group;" ::: "memory")
#define CP_WAIT0()        asm volatile("cp.async.wait_group 0;" ::: "memory")
#define CP_WAIT2()        asm volatile("cp.async.wait_group 2;" ::: "memory")

__device__ __forceinline__ void ldsm4(uint32_t* r, uint32_t addr) {
    asm volatile("ldmatrix.sync.aligned.m8n8.x4.shared.b16 {%0,%1,%2,%3}, [%4];"
        : "=r"(r[0]), "=r"(r[1]), "=r"(r[2]), "=r"(r[3]) : "r"(addr));
}
__device__ __forceinline__ void mma16816h(float* d, const uint32_t* a, const uint32_t* b) {
    asm volatile("mma.sync.aligned.m16n8k16.row.col.f32.f16.f16.f32 "
        "{%0,%1,%2,%3}, {%4,%5,%6,%7}, {%8,%9}, {%0,%1,%2,%3};"
        : "+f"(d[0]), "+f"(d[1]), "+f"(d[2]), "+f"(d[3])
        : "r"(a[0]), "r"(a[1]), "r"(a[2]), "r"(a[3]), "r"(b[0]), "r"(b[1]));
}

// ---------------------------------------------------------------------------
// Kernel 0: weight prep.
// ---------------------------------------------------------------------------
__global__ void __launch_bounds__(256) prep_w_kernel(
    const float* __restrict__ wgi, const float* __restrict__ wpi,
    const float* __restrict__ wgo, const float* __restrict__ wpo)
{
    int idx = blockIdx.x*256 + threadIdx.x;   // 0..65535
    {
        int g = idx >> 14, rem = idx & 16383;
        int row = rem >> 7, k = rem & 127;
        int col = g*64 + (row >> 1);
        float v = (row & 1) ? wpi[k*256 + col] : wgi[k*256 + col];
        g_wcI[idx] = __float2half_rn(v);
    }
    if (idx < 16384) {
        int n = idx >> 7, k = idx & 127;
        g_wgo16[idx] = __float2half_rn(wgo[k*128 + n]);
        g_wpo16[idx] = __float2half_rn(wpo[k*128 + n]);
    }
}

// ---------------------------------------------------------------------------
// Kernel 1: proj5 — persistent; 64-token tiles; 5 weight chunks smem-resident;
// SINGLE-pass fp16 HMMA (A = fp16 LN(x), hi only).
// ---------------------------------------------------------------------------
#define PROW   272
#define PTILE  (128*PROW)         // 34816
#define ATILE  (64*PROW)          // 17408
#define P5_A    0
#define P5_B    ATILE                      // 17408
#define P5_TP   (P5_B + 5*PTILE)           // 191488
#define P5_SMEM (P5_TP + 64*68*4)          // 208896
#define NP5     (NTOK/64)                  // 9216

__global__ void __launch_bounds__(256) proj5_kernel(
    const float* __restrict__ x, const float* __restrict__ mask,
    const float* __restrict__ nw, const float* __restrict__ nb)
{
    extern __shared__ char sm[];
    const uint32_t base = smem_u32(sm);
    const int tid = threadIdx.x;
    const int bid = blockIdx.x;

    const int wid  = tid >> 5;
    const int lane = tid & 31;
    const int m_base = (wid >> 2) * 32;
    const int n_base = (wid & 3) * 32;
    const int a_row  = lane & 15;
    const int a_half = lane >> 4;
    const int b_quad = lane >> 3;
    const int b_row  = (b_quad >> 1)*8 + (lane & 7);
    const int b_half = b_quad & 1;

    // --- load ALL 5 B chunks once ---
    const __half* csrc[5] = { g_wcI, g_wcI + 16384, g_wcI + 32768,
                              g_wcI + 49152, g_wgo16 };
    for (int cc = 0; cc < 5; cc++) {
        const __half* s = csrc[cc];
        uint32_t dst = base + P5_B + cc*PTILE;
        #pragma unroll
        for (int rep = 0; rep < 8; rep++) {
            int it = tid + rep*256;
            int row = it >> 4, q = it & 15;
            CP_ASYNC16(dst + row*PROW + q*16, (const char*)(s + row*128) + q*16);
        }
    }
    CP_COMMIT();
    CP_WAIT0();
    __syncthreads();

    const int tl = tid >> 2, qq = tid & 3;    // LN: 4 threads per token

    for (int tile = bid; tile < NP5; tile += NSM) {
        const int t0 = tile * 64;

        // --- LN(x) direct from gmem -> fp16 A (hi only) ---
        {
            const float* xrow = x + (size_t)(t0 + tl)*CCH + qq*32;
            float v[32];
            float s = 0.f;
            #pragma unroll
            for (int i = 0; i < 8; i++) {
                float4 f = __ldg((const float4*)(xrow + i*4));
                v[i*4]=f.x; v[i*4+1]=f.y; v[i*4+2]=f.z; v[i*4+3]=f.w;
                s += f.x + f.y + f.z + f.w;
            }
            s += __shfl_xor_sync(0xFFFFFFFFu, s, 1);
            s += __shfl_xor_sync(0xFFFFFFFFu, s, 2);
            float m = s * (1.f/128.f);
            float q2 = 0.f;
            #pragma unroll
            for (int i = 0; i < 32; i++) { float d = v[i]-m; q2 += d*d; }
            q2 += __shfl_xor_sync(0xFFFFFFFFu, q2, 1);
            q2 += __shfl_xor_sync(0xFFFFFFFFu, q2, 2);
            float rs = rsqrtf(q2 * (1.f/128.f) + 1e-5f);

            #pragma unroll
            for (int i = 0; i < 16; i++) {
                int k = qq*32 + i*2;
                float v0 = (v[i*2]   - m)*rs*__ldg(&nw[k])   + __ldg(&nb[k]);
                float v1 = (v[i*2+1] - m)*rs*__ldg(&nw[k+1]) + __ldg(&nb[k+1]);
                __half2 hh;
                hh.x = __float2half_rn(v0);
                hh.y = __float2half_rn(v1);
                *(__half2*)(sm + P5_A + tl*PROW + k*2) = hh;
            }
        }
        __syncthreads();

        // --- 5 chunks, B resident, single pass ---
        #pragma unroll
        for (int c = 0; c < 5; c++) {
            const uint32_t sb = base + P5_B + c*PTILE;
            float acc[2][4][4];
            #pragma unroll
            for (int mt = 0; mt < 2; mt++)
                #pragma unroll
                for (int nt = 0; nt < 4; nt++)
                    #pragma unroll
                    for (int r = 0; r < 4; r++) acc[mt][nt][r] = 0.f;

            #pragma unroll
            for (int ks = 0; ks < 8; ks++) {
                const uint32_t koff = ks*32;
                uint32_t Ah[2][4];
                #pragma unroll
                for (int mt = 0; mt < 2; mt++) {
                    uint32_t r = (m_base + mt*16 + a_row)*PROW + koff + a_half*16;
                    ldsm4(Ah[mt], base + P5_A + r);
                }
                uint32_t Bf[4][2];
                #pragma unroll
                for (int p = 0; p < 2; p++) {
                    uint32_t r = (n_base + p*16 + b_row)*PROW + koff + b_half*16;
                    uint32_t th[4];
                    ldsm4(th, sb + r);
                    Bf[2*p][0]   = th[0]; Bf[2*p][1]   = th[1];
                    Bf[2*p+1][0] = th[2]; Bf[2*p+1][1] = th[3];
                }
                #pragma unroll
                for (int mt = 0; mt < 2; mt++)
                    #pragma unroll
                    for (int nt = 0; nt < 4; nt++) mma16816h(acc[mt][nt], Ah[mt], Bf[nt]);
            }

            if (c < 4) {
                // a/b epilogue: hi-only via transpose buffer
                uint32_t* tp = (uint32_t*)(sm + P5_TP);
                const bool isA = (c < 2);
                const int cgl = (c & 1) * 64;
                #pragma unroll
                for (int mt = 0; mt < 2; mt++) {
                    #pragma unroll
                    for (int rp = 0; rp < 2; rp++) {
                        int t_loc = m_base + mt*16 + rp*8 + (lane >> 2);
                        float mk = isA ? __ldg(&mask[t0 + t_loc]) : 1.f;
                        #pragma unroll
                        for (int nt = 0; nt < 4; nt++) {
                            int c_loc = (n_base >> 1) + nt*4 + (lane & 3);
                            float val = sigmoidf_(acc[mt][nt][rp*2]) * acc[mt][nt][rp*2+1] * mk;
                            tp[c_loc*68 + t_loc] =
                                (uint32_t)__half_as_ushort(__float2half_rn(val));
                        }
                    }
                }
                __syncthreads();

                #pragma unroll
                for (int rep = 0; rep < 8; rep++) {
                    int idx = tid + rep*256;        // 0..2047
                    int cl = idx >> 5, t2 = idx & 31;
                    uint32_t u0 = tp[cl*68 + t2*2];
                    uint32_t u1 = tp[cl*68 + t2*2 + 1];
                    uint32_t hi2 = (u0 & 0xFFFFu) | (u1 << 16);
                    size_t o = ((size_t)(cgl + cl)*NTOK + t0) >> 1;
                    if (isA) ((uint32_t*)g_ahi)[o + t2] = hi2;
                    else     ((uint32_t*)g_bhi)[o + t2] = hi2;
                }
                __syncthreads();
            } else {
                // out-gate epilogue: token-major sigmoid -> fp16
                #pragma unroll
                for (int mt = 0; mt < 2; mt++) {
                    #pragma unroll
                    for (int rp = 0; rp < 2; rp++) {
                        int t = t0 + m_base + mt*16 + rp*8 + (lane >> 2);
                        #pragma unroll
                        for (int nt = 0; nt < 4; nt++) {
                            int ch = n_base + nt*8 + (lane & 3)*2;
                            __half2 f;
                            f.x = __float2half_rn(sigmoidf_(acc[mt][nt][rp*2]));
                            f.y = __float2half_rn(sigmoidf_(acc[mt][nt][rp*2+1]));
                            *(__half2*)&g_gate16[(size_t)t*CCH + ch] = f;
                        }
                    }
                }
            }
        }
        __syncthreads();
    }
}

// ---------------------------------------------------------------------------
// Kernel 2: tri einsum, single-pass fp16, K-chunk=128, triple buf, fp16 out.
// ---------------------------------------------------------------------------
#define TILE2   (128*PROW)          // 34816
#define CHUNKT  (2*TILE2)           // 69632
#define TRI_SMEM (3*CHUNKT)         // 208896

__device__ __forceinline__ void tri_load_chunk(
    uint32_t sbuf, const __half* sA, const __half* sB, int kk, int tid)
{
    const __half* srcs[2] = {sA, sB};
    #pragma unroll
    for (int rep = 0; rep < 16; rep++) {
        int it   = tid + rep*256;             // 0..4095
        int tile = it >> 11;
        int row  = (it >> 4) & 127;
        int q    = it & 15;
        const __half* gp = srcs[tile] + (size_t)row*SDIM + kk + q*8;
        CP_ASYNC16(sbuf + tile*TILE2 + row*PROW + q*16, gp);
    }
}

__global__ void __launch_bounds__(256) tri_mma_kernel()
{
    extern __shared__ char dynsm[];
    const uint32_t base = smem_u32(dynsm);

    const int tid  = threadIdx.x;
    const int wid  = tid >> 5;
    const int lane = tid & 31;
    const int m_base = (wid >> 2) * 64;
    const int n_base = (wid & 3) * 32;

    const int c  = blockIdx.y;
    const int i0 = (blockIdx.x / 6) * 128;
    const int j0 = (blockIdx.x % 6) * 128;

    const __half* sAh = g_ahi + (size_t)c*NTOK + (size_t)i0*SDIM;
    const __half* sBh = g_bhi + (size_t)c*NTOK + (size_t)j0*SDIM;

    float acc[4][4][4];
    #pragma unroll
    for (int mt = 0; mt < 4; mt++)
        #pragma unroll
        for (int nt = 0; nt < 4; nt++)
            #pragma unroll
            for (int r = 0; r < 4; r++) acc[mt][nt][r] = 0.f;

    const int a_row  = lane & 15;
    const int a_half = lane >> 4;
    const int b_quad = lane >> 3;
    const int b_row  = (b_quad >> 1) * 8 + (lane & 7);
    const int b_half = b_quad & 1;

    tri_load_chunk(base + 0*CHUNKT, sAh, sBh, 0,   tid); CP_COMMIT();
    tri_load_chunk(base + 1*CHUNKT, sAh, sBh, 128, tid); CP_COMMIT();

    for (int n = 0; n < 6; n++) {
        if (n + 2 < 6)
            tri_load_chunk(base + ((n+2)%3)*CHUNKT, sAh, sBh, (n+2)*128, tid);
        CP_COMMIT();
        CP_WAIT2();
        __syncthreads();

        const uint32_t sb = base + (n%3)*CHUNKT;
        #pragma unroll
        for (int ks = 0; ks < 8; ks++) {
            uint32_t Ah[4][4], Bh[4][2];
            const uint32_t koff = ks*32;
            #pragma unroll
            for (int mt = 0; mt < 4; mt++) {
                uint32_t r = (m_base + mt*16 + a_row)*PROW + koff + a_half*16;
                ldsm4(Ah[mt], sb + r);
            }
            #pragma unroll
            for (int p = 0; p < 2; p++) {
                uint32_t r = (n_base + p*16 + b_row)*PROW + koff + b_half*16;
                uint32_t th[4];
                ldsm4(th, sb + TILE2 + r);
                Bh[2*p][0]   = th[0]; Bh[2*p][1]   = th[1];
                Bh[2*p+1][0] = th[2]; Bh[2*p+1][1] = th[3];
            }
            #pragma unroll
            for (int mt = 0; mt < 4; mt++)
                #pragma unroll
                for (int nt = 0; nt < 4; nt++)
                    mma16816h(acc[mt][nt], Ah[mt], Bh[nt]);
        }
        __syncthreads();
    }

    __half* T = g_tri16 + (size_t)c*NTOK;
    const int er = i0 + m_base + (lane >> 2);
    const int ec2 = j0 + n_base + (lane & 3)*2;
    #pragma unroll
    for (int mt = 0; mt < 4; mt++) {
        #pragma unroll
        for (int nt = 0; nt < 4; nt++) {
            int rr = er + mt*16;
            int cc = ec2 + nt*8;
            __half2 v0; v0.x = __float2half_rn(acc[mt][nt][0]);
                        v0.y = __float2half_rn(acc[mt][nt][1]);
            __half2 v1; v1.x = __float2half_rn(acc[mt][nt][2]);
                        v1.y = __float2half_rn(acc[mt][nt][3]);
            *(__half2*)&T[(size_t)rr*SDIM + cc]     = v0;
            *(__half2*)&T[(size_t)(rr+8)*SDIM + cc] = v1;
        }
    }
}

// ---------------------------------------------------------------------------
// Kernel 3: out2 — persistent, 256 thr, 64-token tiles, 2 CTAs/SM.
// tri fp16 staging, single-pass fp16 MMA, gate fp16 LDG.
// ---------------------------------------------------------------------------
#define TROW     144                    // 64 tok * 2B + 16 pad
#define O2_TRI   0                      // 128 ch x 144B = 18432
#define O2_A     18432                  // 64 x 272 = 17408
#define O2_B     (O2_A + ATILE)         // 35840
#define O2_SMEM  (O2_B + PTILE)         // 70656  (2 CTAs/SM)
#define NOT64    (NTOK/64)              // 9216
#define OGRID    (2*NSM)                // 296

__global__ void __launch_bounds__(256) out2_kernel(
    const float* __restrict__ now, const float* __restrict__ nob,
    float* __restrict__ out)
{
    extern __shared__ char sm[];
    const uint32_t base = smem_u32(sm);
    const int tid = threadIdx.x;
    const int bid = blockIdx.x;

    // one-time B (wpo^T fp16)
    #pragma unroll
    for (int rep = 0; rep < 8; rep++) {
        int it = tid + rep*256;
        int row = it >> 4, q = it & 15;
        CP_ASYNC16(base + O2_B + row*PROW + q*16,
                   (const char*)(g_wpo16 + row*128) + q*16);
    }
    // first tri tile (fp16, 64 tokens)
    {
        int t0 = bid * 64;
        #pragma unroll
        for (int rep = 0; rep < 4; rep++) {
            int it = tid + rep*256;           // 0..1023
            int ch = it >> 3, q = it & 7;
            CP_ASYNC16(base + O2_TRI + ch*TROW + q*16,
                       g_tri16 + (size_t)ch*NTOK + t0 + q*8);
        }
    }
    CP_COMMIT();

    const int wid  = tid >> 5;
    const int lane = tid & 31;
    const int m_base = (wid >> 2) * 32;
    const int n_base = (wid & 3) * 32;
    const int a_row  = lane & 15;
    const int a_half = lane >> 4;
    const int b_quad = lane >> 3;
    const int b_row  = (b_quad >> 1)*8 + (lane & 7);
    const int b_half = b_quad & 1;
    const int er = m_base + (lane >> 2);
    const int ec = n_base + (lane & 3)*2;

    const __half* trs = (const __half*)(sm + O2_TRI);
    const int tl = tid >> 2, qq = tid & 3;

    for (int tile = bid; tile < NOT64; tile += OGRID) {
        const int t0 = tile * 64;
        CP_WAIT0();
        __syncthreads();

        // LN over channels (fp16 staging) -> fp16 A [t][ch]
        {
            float s = 0.f;
            float vch[32];
            #pragma unroll
            for (int j = 0; j < 32; j++) {
                vch[j] = __half2float(trs[(qq*32 + j)*72 + tl]);
                s += vch[j];
            }
            s += __shfl_xor_sync(0xFFFFFFFFu, s, 1);
            s += __shfl_xor_sync(0xFFFFFFFFu, s, 2);
            float m = s * (1.f/128.f);
            float q2 = 0.f;
            #pragma unroll
            for (int j = 0; j < 32; j++) {
                float d = vch[j] - m;
                q2 += d*d;
            }
            q2 += __shfl_xor_sync(0xFFFFFFFFu, q2, 1);
            q2 += __shfl_xor_sync(0xFFFFFFFFu, q2, 2);
            float rs = rsqrtf(q2 * (1.f/128.f) + 1e-5f);

            #pragma unroll
            for (int j = 0; j < 16; j++) {
                int ch = qq*32 + j*2;
                float v0 = (vch[j*2]   - m)*rs*__ldg(&now[ch])   + __ldg(&nob[ch]);
                float v1 = (vch[j*2+1] - m)*rs*__ldg(&now[ch+1]) + __ldg(&nob[ch+1]);
                __half2 hh;
                hh.x = __float2half_rn(v0);
                hh.y = __float2half_rn(v1);
                *(__half2*)(sm + O2_A + tl*PROW + ch*2) = hh;
            }
        }
        __syncthreads();

        // prefetch next tri tile into staging
        if (tile + OGRID < NOT64) {
            int nt0 = (tile + OGRID) * 64;
            #pragma unroll
            for (int rep = 0; rep < 4; rep++) {
                int it = tid + rep*256;
                int ch = it >> 3, q = it & 7;
                CP_ASYNC16(base + O2_TRI + ch*TROW + q*16,
                           g_tri16 + (size_t)ch*NTOK + nt0 + q*8);
            }
        }
        CP_COMMIT();

        float acc[2][4][4];
        #pragma unroll
        for (int mt = 0; mt < 2; mt++)
            #pragma unroll
            for (int nt = 0; nt < 4; nt++)
                #pragma unroll
                for (int r = 0; r < 4; r++) acc[mt][nt][r] = 0.f;

        #pragma unroll
        for (int ks = 0; ks < 8; ks++) {
            const uint32_t koff = ks*32;
            uint32_t Ah[2][4];
            #pragma unroll
            for (int mt = 0; mt < 2; mt++) {
                uint32_t r = (m_base + mt*16 + a_row)*PROW + koff + a_half*16;
                ldsm4(Ah[mt], base + O2_A + r);
            }
            uint32_t Bf[4][2];
            #pragma unroll
            for (int p = 0; p < 2; p++) {
                uint32_t r = (n_base + p*16 + b_row)*PROW + koff + b_half*16;
                uint32_t th[4];
                ldsm4(th, base + O2_B + r);
                Bf[2*p][0]   = th[0]; Bf[2*p][1]   = th[1];
                Bf[2*p+1][0] = th[2]; Bf[2*p+1][1] = th[3];
            }
            #pragma unroll
            for (int mt = 0; mt < 2; mt++)
                #pragma unroll
                for (int nt = 0; nt < 4; nt++) mma16816h(acc[mt][nt], Ah[mt], Bf[nt]);
        }

        // epilogue: gate fp16 via direct LDG, out stores
        #pragma unroll
        for (int mt = 0; mt < 2; mt++) {
            #pragma unroll
            for (int rp = 0; rp < 2; rp++) {
                int t = t0 + er + mt*16 + rp*8;
                #pragma unroll
                for (int nt = 0; nt < 4; nt++) {
                    int cc = ec + nt*8;
                    __half2 gh = __ldg((const __half2*)&g_gate16[(size_t)t*CCH + cc]);
                    float2 o = make_float2(acc[mt][nt][rp*2]   * __half2float(gh.x),
                                           acc[mt][nt][rp*2+1] * __half2float(gh.y));
                    *(float2*)&out[(size_t)t*CCH + cc] = o;
                }
            }
        }
        __syncthreads();
    }
}

// ---------------------------------------------------------------------------
extern "C" void kernel_launch(void* const* d_in, const int* in_sizes, int n_in,
                              void* d_out, int out_size)
{
    const float* x    = (const float*)d_in[0];
    const float* mask = (const float*)d_in[1];
    const float* niw  = (const float*)d_in[2];
    const float* nib  = (const float*)d_in[3];
    const float* wgi  = (const float*)d_in[4];
    const float* wpi  = (const float*)d_in[5];
    const float* now  = (const float*)d_in[6];
    const float* nob  = (const float*)d_in[7];
    const float* wgo  = (const float*)d_in[8];
    const float* wpo  = (const float*)d_in[9];
    float* out = (float*)d_out;

    cudaFuncSetAttribute(proj5_kernel,
        cudaFuncAttributeMaxDynamicSharedMemorySize, P5_SMEM);
    cudaFuncSetAttribute(tri_mma_kernel,
        cudaFuncAttributeMaxDynamicSharedMemorySize, TRI_SMEM);
    cudaFuncSetAttribute(out2_kernel,
        cudaFuncAttributeMaxDynamicSharedMemorySize, O2_SMEM);

    prep_w_kernel<<<256, 256>>>(wgi, wpi, wgo, wpo);
    proj5_kernel<<<NSM, 256, P5_SMEM>>>(x, mask, niw, nib);
    tri_mma_kernel<<<dim3(36, 128), 256, TRI_SMEM>>>();
    out2_kernel<<<OGRID, 256, O2_SMEM>>>(now, nob, out);
}